// round 6
// baseline (speedup 1.0000x reference)
#include <cuda_runtime.h>
#include <cuda_bf16.h>
#include <math.h>
#include <stdint.h>

#define NN   65536
#define BB   1024
#define EE   2097152
#define EEG  524288
#define DIM  128

// ======================= portable PTX helpers ================================
__device__ __forceinline__ uint32_t smem_to_u32(const void* p) {
    uint32_t a;
    asm("{ .reg .u64 t; cvta.to.shared.u64 t, %1; cvt.u32.u64 %0, t; }" : "=r"(a) : "l"(p));
    return a;
}

__device__ __forceinline__ void ldsm4(uint32_t* r, uint32_t addr) {
    asm volatile("ldmatrix.sync.aligned.m8n8.x4.shared.b16 {%0,%1,%2,%3}, [%4];"
                 : "=r"(r[0]), "=r"(r[1]), "=r"(r[2]), "=r"(r[3]) : "r"(addr));
}

__device__ __forceinline__ void mma16816(float* c, const uint32_t* a, const uint32_t* b) {
    asm volatile("mma.sync.aligned.m16n8k16.row.col.f32.bf16.bf16.f32 "
                 "{%0,%1,%2,%3}, {%4,%5,%6,%7}, {%8,%9}, {%0,%1,%2,%3};"
                 : "+f"(c[0]), "+f"(c[1]), "+f"(c[2]), "+f"(c[3])
                 : "r"(a[0]), "r"(a[1]), "r"(a[2]), "r"(a[3]), "r"(b[0]), "r"(b[1]));
}

__device__ __forceinline__ void cp_async16(uint32_t dst, const void* src) {
    asm volatile("cp.async.cg.shared.global [%0], [%1], 16;" :: "r"(dst), "l"(src) : "memory");
}

// ======================= static scratch ======================================
__device__ float d_h   [(size_t)NN * DIM];   // node features (fp32)
__device__ float d_lg  [(size_t)NN * DIM];   // logit-head features (fp32)

__device__ __nv_bfloat16 d_mHi[(size_t)NN * DIM], d_mLo[(size_t)NN * DIM];
__device__ __nv_bfloat16 d_gHi[(size_t)NN * DIM], d_gLo[(size_t)NN * DIM];

// converted transposed weights (bf16 hi/lo), layout [n][K]
__device__ __nv_bfloat16 d_wt1h[7*128*128], d_wt1l[7*128*128];
__device__ __nv_bfloat16 d_wt2h[7*128*128], d_wt2l[7*128*128];
__device__ __nv_bfloat16 d_wt3h[7*128*256], d_wt3l[7*128*256];
__device__ __nv_bfloat16 d_wtlh[128*128],   d_wtll[128*128];

__device__ int d_csrM[EE];
__device__ int d_csrG[EEG];
__device__ int d_offM[NN + 1];
__device__ int d_offG[NN + 1];
__device__ int d_curM[NN];
__device__ int d_curG[NN];
__device__ int d_cntOutM[NN], d_cntInM[NN], d_cntOutG[NN], d_cntInG[NN];
__device__ float d_s1[NN], d_r1[NN], d_c1[NN];
__device__ float d_s2[NN], d_r2[NN], d_c2[NN];

// ======================= weight convert + counter zero (one launch) ==========
#define WT_S1 (7*16384)
#define WT_S3 (7*32768)
#define WT_TOTAL (2*WT_S1 + WT_S3 + 16384)
__global__ void k_wt_all(const float* __restrict__ w1, const float* __restrict__ w2,
                         const float* __restrict__ w3, const float* __restrict__ wl) {
    int id = blockIdx.x * blockDim.x + threadIdx.x;
    if (id < NN) { d_cntOutM[id] = 0; d_cntInM[id] = 0; d_cntOutG[id] = 0; d_cntInG[id] = 0; }
    float v;
    __nv_bfloat16 *hi, *lo;
    int oidx;
    if (id < WT_S1) {
        int layer = id >> 14, w = id & 16383;
        int n = w >> 7, k = w & 127;
        v = w1[(size_t)(layer << 14) + k * 128 + n];
        hi = d_wt1h; lo = d_wt1l; oidx = (layer << 14) + n * 128 + k;
    } else if (id < 2 * WT_S1) {
        int id2 = id - WT_S1;
        int layer = id2 >> 14, w = id2 & 16383;
        int n = w >> 7, k = w & 127;
        v = w2[(size_t)(layer << 14) + k * 128 + n];
        hi = d_wt2h; lo = d_wt2l; oidx = (layer << 14) + n * 128 + k;
    } else if (id < 2 * WT_S1 + WT_S3) {
        int id3 = id - 2 * WT_S1;
        int layer = id3 >> 15, w = id3 & 32767;
        int n = w >> 8, k = w & 255;
        v = w3[(size_t)(layer << 15) + k * 128 + n];
        hi = d_wt3h; lo = d_wt3l; oidx = (layer << 15) + n * 256 + k;
    } else if (id < WT_TOTAL) {
        int id4 = id - (2 * WT_S1 + WT_S3);
        int n = id4 >> 7, k = id4 & 127;
        v = wl[k * 128 + n];
        hi = d_wtlh; lo = d_wtll; oidx = n * 128 + k;
    } else return;
    __nv_bfloat16 h = __float2bfloat16(v);
    hi[oidx] = h;
    lo[oidx] = __float2bfloat16(v - __bfloat162float(h));
}

// ======================= precompute ==========================================
__global__ void k_histB(const int* __restrict__ snd, const int* __restrict__ rcv,
                        const int* __restrict__ gsnd, const int* __restrict__ grcv) {
    int e = blockIdx.x * blockDim.x + threadIdx.x;
    if (e < EE) {
        atomicAdd(&d_cntOutM[snd[e]], 1); atomicAdd(&d_cntInM[rcv[e]], 1);
    } else if (e < EE + EEG) {
        int g = e - EE;
        atomicAdd(&d_cntOutG[gsnd[g]], 1); atomicAdd(&d_cntInG[grcv[g]], 1);
    }
}

// scan + norms + c-init, two blocks: 0 = move, 1 = grid
__global__ void k_scanB() {
    int isG = blockIdx.x;
    const int* cnt  = isG ? d_cntInG  : d_cntInM;
    const int* cntO = isG ? d_cntOutG : d_cntOutM;
    int* off = isG ? d_offG : d_offM;
    int* cur = isG ? d_curG : d_curM;
    float* sA = isG ? d_s2 : d_s1;
    float* cA = isG ? d_c2 : d_c1;
    float* rA = isG ? d_r2 : d_r1;
    __shared__ int ps[1024];
    int t = threadIdx.x;
    int base = t * 64;
    int s = 0;
    for (int j = 0; j < 64; j++) {
        int cv = cnt[base + j];
        s += cv;
        float sv = rsqrtf((float)(cntO[base + j] + 1));
        sA[base + j] = sv;
        cA[base + j] = sv;                       // self-edge term; scatter adds rest
        rA[base + j] = rsqrtf((float)(cv + 1));
    }
    ps[t] = s;
    __syncthreads();
    for (int d = 1; d < 1024; d <<= 1) {
        int v = 0;
        if (t >= d) v = ps[t - d];
        __syncthreads();
        ps[t] += v;
        __syncthreads();
    }
    int run = (t == 0) ? 0 : ps[t - 1];
    for (int j = 0; j < 64; j++) {
        off[base + j] = run;
        cur[base + j] = run;
        run += cnt[base + j];
    }
    if (t == 1023) off[NN] = run;
}

// scatter both edge sets + fold in csum (c[r] += s[snd]) via float atomics
__global__ void k_scatB(const int* __restrict__ snd, const int* __restrict__ rcv,
                        const int* __restrict__ gsnd, const int* __restrict__ grcv) {
    int e = blockIdx.x * blockDim.x + threadIdx.x;
    if (e < EE) {
        int s = snd[e], r = rcv[e];
        int p = atomicAdd(&d_curM[r], 1);
        d_csrM[p] = s;
        atomicAdd(&d_c1[r], d_s1[s]);
    } else if (e < EE + EEG) {
        int g = e - EE;
        int s = gsnd[g], r = grcv[g];
        int p = atomicAdd(&d_curG[r], 1);
        d_csrG[p] = s;
        atomicAdd(&d_c2[r], d_s2[s]);
    }
}

// ======================= embedding ==========================================
__global__ void k_embed(const int* __restrict__ nodes, const float* __restrict__ embed,
                        float* __restrict__ h) {
    int i = blockIdx.x * blockDim.x + threadIdx.x;
    if (i < NN * 32) {
        int node = i >> 5;
        int c    = i & 31;
        ((float4*)h)[i] = ((const float4*)embed)[nodes[node] * 32 + c];
    }
}

// ======================= pull aggregation (unroll-4 prefetch) ================
__global__ void k_aggB(const float* __restrict__ h) {
    int gw   = (blockIdx.x * blockDim.x + threadIdx.x) >> 5;  // 0 .. 2*NN-1
    int lane = threadIdx.x & 31;
    int isG  = gw >= NN;
    int node = gw - (isG ? NN : 0);
    if (gw >= 2 * NN) return;
    const int* off = isG ? d_offG : d_offM;
    const int* csr = isG ? d_csrG : d_csrM;
    const float* sn = isG ? d_s2 : d_s1;
    __nv_bfloat16* oHi = isG ? d_gHi : d_mHi;
    __nv_bfloat16* oLo = isG ? d_gLo : d_mLo;

    const float4* h4 = (const float4*)h;
    float s0 = sn[node];
    float4 a = h4[(size_t)node * 32 + lane];
    float4 acc;
    acc.x = a.x * s0; acc.y = a.y * s0; acc.z = a.z * s0; acc.w = a.w * s0;
    int e  = off[node];
    int e1 = off[node + 1];
    for (; e + 4 <= e1; e += 4) {
        int i0 = csr[e], i1 = csr[e + 1], i2 = csr[e + 2], i3 = csr[e + 3];
        float c0 = sn[i0], c1 = sn[i1], c2 = sn[i2], c3 = sn[i3];
        float4 v0 = h4[(size_t)i0 * 32 + lane];
        float4 v1 = h4[(size_t)i1 * 32 + lane];
        float4 v2 = h4[(size_t)i2 * 32 + lane];
        float4 v3 = h4[(size_t)i3 * 32 + lane];
        acc.x = fmaf(v0.x, c0, acc.x); acc.y = fmaf(v0.y, c0, acc.y);
        acc.z = fmaf(v0.z, c0, acc.z); acc.w = fmaf(v0.w, c0, acc.w);
        acc.x = fmaf(v1.x, c1, acc.x); acc.y = fmaf(v1.y, c1, acc.y);
        acc.z = fmaf(v1.z, c1, acc.z); acc.w = fmaf(v1.w, c1, acc.w);
        acc.x = fmaf(v2.x, c2, acc.x); acc.y = fmaf(v2.y, c2, acc.y);
        acc.z = fmaf(v2.z, c2, acc.z); acc.w = fmaf(v2.w, c2, acc.w);
        acc.x = fmaf(v3.x, c3, acc.x); acc.y = fmaf(v3.y, c3, acc.y);
        acc.z = fmaf(v3.z, c3, acc.z); acc.w = fmaf(v3.w, c3, acc.w);
    }
    for (; e < e1; e++) {
        int   s  = csr[e];
        float sc = sn[s];
        float4 v = h4[(size_t)s * 32 + lane];
        acc.x = fmaf(v.x, sc, acc.x);
        acc.y = fmaf(v.y, sc, acc.y);
        acc.z = fmaf(v.z, sc, acc.z);
        acc.w = fmaf(v.w, sc, acc.w);
    }
    __nv_bfloat16 hv[4], lv[4];
    float av[4] = {acc.x, acc.y, acc.z, acc.w};
#pragma unroll
    for (int j = 0; j < 4; j++) {
        hv[j] = __float2bfloat16(av[j]);
        lv[j] = __float2bfloat16(av[j] - __bfloat162float(hv[j]));
    }
    size_t p = (size_t)node * 128 + lane * 4;
    *(uint2*)&oHi[p] = *(uint2*)hv;
    *(uint2*)&oLo[p] = *(uint2*)lv;
}

// ======================= HMMA GEMM (cp.async double-buffered) ================
#define SLICE_BYTES 65536
#define SM_TOTAL    131072

__device__ __forceinline__ void stage_slice(
    uint32_t sbuf,
    const __nv_bfloat16* Ah, const __nv_bfloat16* Al,
    const __nv_bfloat16* wtHi, const __nv_bfloat16* wtLo,
    int rowBase, int K, int c, int ks, int tid) {
#pragma unroll
    for (int j = 0; j < 16; j++) {
        int tile = j >> 2;
        int cidx = tid + (j & 3) * 256;
        int r = cidx >> 3, ch = cidx & 7;
        uint32_t dst = sbuf + tile * 16384 + (uint32_t)r * 128 +
                       (uint32_t)((ch * 16) ^ ((r & 7) << 4));
        const __nv_bfloat16* src;
        if (tile == 0)      src = Ah   + (size_t)(rowBase + r) * 128 + ks * 64 + ch * 8;
        else if (tile == 1) src = Al   + (size_t)(rowBase + r) * 128 + ks * 64 + ch * 8;
        else if (tile == 2) src = wtHi + (size_t)r * K + c * 128 + ks * 64 + ch * 8;
        else                src = wtLo + (size_t)r * K + c * 128 + ks * 64 + ch * 8;
        cp_async16(dst, src);
    }
    asm volatile("cp.async.commit_group;" ::: "memory");
}

__device__ __forceinline__ void mma_compute_slice(
    uint32_t base, int ra_base, uint32_t kxA, uint32_t xorA,
    int rb_base, uint32_t kxB, uint32_t xorB, float acc[16][4]) {
#pragma unroll
    for (int ka = 0; ka < 4; ka++) {
        uint32_t fAh[2][4], fAl[2][4];
#pragma unroll
        for (int ma = 0; ma < 2; ma++) {
            uint32_t off = (uint32_t)(ra_base + ma * 16) * 128 +
                           (((uint32_t)(ka * 32) + kxA) ^ xorA);
            ldsm4(fAh[ma], base + off);
            ldsm4(fAl[ma], base + 16384 + off);
        }
#pragma unroll
        for (int nb = 0; nb < 4; nb++) {
            uint32_t off = (uint32_t)(rb_base + nb * 16) * 128 +
                           (((uint32_t)(ka * 32) + kxB) ^ xorB);
            uint32_t wh[4], wl[4];
            ldsm4(wh, base + 32768 + off);
            ldsm4(wl, base + 49152 + off);
#pragma unroll
            for (int ma = 0; ma < 2; ma++) {
                float* a0 = acc[ma * 8 + nb * 2];
                float* a1 = acc[ma * 8 + nb * 2 + 1];
                mma16816(a0, fAh[ma], wh);
                mma16816(a1, fAh[ma], wh + 2);
                mma16816(a0, fAl[ma], wh);
                mma16816(a1, fAl[ma], wh + 2);
                mma16816(a0, fAh[ma], wl);
                mma16816(a1, fAh[ma], wl + 2);
            }
        }
    }
}

__device__ __forceinline__ void mma_body(
    const __nv_bfloat16* aHi, const __nv_bfloat16* aLo,
    const __nv_bfloat16* gHi, const __nv_bfloat16* gLo,
    const __nv_bfloat16* wtHi, const __nv_bfloat16* wtLo,
    int K, const float* bias, const float* crow, const float* rrow,
    int relu, float* outF, __nv_bfloat16* outHi, __nv_bfloat16* outLo,
    int rowBase, char* smem) {
    uint32_t sb = smem_to_u32(smem);
    int tid = threadIdx.x;
    int wid = tid >> 5;
    int l   = tid & 31;
    int m0 = (wid >> 1) * 32;
    int n0 = (wid & 1) * 64;

    int ra_base = m0 + (l & 7) + ((l >> 3) & 1) * 8;
    uint32_t kxA = ((l >> 4) & 1) * 16;
    uint32_t xorA = (uint32_t)((ra_base & 7) << 4);
    int rb_base = n0 + (l & 7) + ((l >> 4) & 1) * 8;
    uint32_t kxB = ((l >> 3) & 1) * 16;
    uint32_t xorB = (uint32_t)((rb_base & 7) << 4);

    float acc[16][4];
#pragma unroll
    for (int i = 0; i < 16; i++)
#pragma unroll
        for (int j = 0; j < 4; j++) acc[i][j] = 0.f;

    int nslices = K >> 6;
    stage_slice(sb, aHi, aLo, wtHi, wtLo, rowBase, K, 0, 0, tid);
    for (int s = 0; s < nslices; s++) {
        if (s + 1 < nslices) {
            int c = (s + 1) >> 1, ks = (s + 1) & 1;
            stage_slice(sb + ((s + 1) & 1) * SLICE_BYTES,
                        c ? gHi : aHi, c ? gLo : aLo, wtHi, wtLo,
                        rowBase, K, c, ks, tid);
            asm volatile("cp.async.wait_group 1;" ::: "memory");
        } else {
            asm volatile("cp.async.wait_group 0;" ::: "memory");
        }
        __syncthreads();
        mma_compute_slice(sb + (s & 1) * SLICE_BYTES,
                          ra_base, kxA, xorA, rb_base, kxB, xorB, acc);
        __syncthreads();
    }

    int gid = l >> 2, tig = l & 3;
#pragma unroll
    for (int ma = 0; ma < 2; ma++) {
        int r0 = rowBase + m0 + ma * 16 + gid;
        int r1 = r0 + 8;
        float cm0 = crow ? crow[r0] : 1.f, rm0 = rrow ? rrow[r0] : 1.f;
        float cm1 = crow ? crow[r1] : 1.f, rm1 = rrow ? rrow[r1] : 1.f;
#pragma unroll
        for (int na = 0; na < 8; na++) {
            int col = n0 + na * 8 + tig * 2;
            float b0 = bias[col], b1 = bias[col + 1];
            float* ac = acc[ma * 8 + na];
            float o00 = (ac[0] + b0 * cm0) * rm0;
            float o01 = (ac[1] + b1 * cm0) * rm0;
            float o10 = (ac[2] + b0 * cm1) * rm1;
            float o11 = (ac[3] + b1 * cm1) * rm1;
            if (relu) {
                o00 = fmaxf(o00, 0.f); o01 = fmaxf(o01, 0.f);
                o10 = fmaxf(o10, 0.f); o11 = fmaxf(o11, 0.f);
            }
            if (outF) {
                *(float2*)&outF[(size_t)r0 * 128 + col] = make_float2(o00, o01);
                *(float2*)&outF[(size_t)r1 * 128 + col] = make_float2(o10, o11);
            }
            if (outHi) {
                __nv_bfloat16 h00 = __float2bfloat16(o00), h01 = __float2bfloat16(o01);
                __nv_bfloat16 h10 = __float2bfloat16(o10), h11 = __float2bfloat16(o11);
                __nv_bfloat162 hp0; hp0.x = h00; hp0.y = h01;
                __nv_bfloat162 hp1; hp1.x = h10; hp1.y = h11;
                __nv_bfloat162 lp0;
                lp0.x = __float2bfloat16(o00 - __bfloat162float(h00));
                lp0.y = __float2bfloat16(o01 - __bfloat162float(h01));
                __nv_bfloat162 lp1;
                lp1.x = __float2bfloat16(o10 - __bfloat162float(h10));
                lp1.y = __float2bfloat16(o11 - __bfloat162float(h11));
                *(__nv_bfloat162*)&outHi[(size_t)r0 * 128 + col] = hp0;
                *(__nv_bfloat162*)&outHi[(size_t)r1 * 128 + col] = hp1;
                *(__nv_bfloat162*)&outLo[(size_t)r0 * 128 + col] = lp0;
                *(__nv_bfloat162*)&outLo[(size_t)r1 * 128 + col] = lp1;
            }
        }
    }
}

__global__ void __launch_bounds__(256)
k_mmaS(const __nv_bfloat16* aHi, const __nv_bfloat16* aLo,
       const __nv_bfloat16* gHi, const __nv_bfloat16* gLo,
       const __nv_bfloat16* wtHi, const __nv_bfloat16* wtLo,
       int K, const float* bias, const float* crow, const float* rrow,
       int relu, float* outF, __nv_bfloat16* outHi, __nv_bfloat16* outLo) {
    extern __shared__ __align__(16) char smem[];
    mma_body(aHi, aLo, gHi, gLo, wtHi, wtLo, K, bias, crow, rrow,
             relu, outF, outHi, outLo, blockIdx.x * 128, smem);
}

__global__ void __launch_bounds__(256)
k_mmaD(const __nv_bfloat16* a1Hi, const __nv_bfloat16* a1Lo,
       const __nv_bfloat16* wt1Hi, const __nv_bfloat16* wt1Lo,
       const float* bias1, const float* crow1, const float* rrow1,
       __nv_bfloat16* out1Hi, __nv_bfloat16* out1Lo,
       const __nv_bfloat16* a2Hi, const __nv_bfloat16* a2Lo,
       const __nv_bfloat16* wt2Hi, const __nv_bfloat16* wt2Lo,
       const float* bias2, const float* crow2, const float* rrow2,
       __nv_bfloat16* out2Hi, __nv_bfloat16* out2Lo) {
    extern __shared__ __align__(16) char smem[];
    if (blockIdx.x < 512)
        mma_body(a1Hi, a1Lo, nullptr, nullptr, wt1Hi, wt1Lo, 128,
                 bias1, crow1, rrow1, 0, nullptr, out1Hi, out1Lo,
                 blockIdx.x * 128, smem);
    else
        mma_body(a2Hi, a2Lo, nullptr, nullptr, wt2Hi, wt2Lo, 128,
                 bias2, crow2, rrow2, 0, nullptr, out2Hi, out2Lo,
                 (blockIdx.x - 512) * 128, smem);
}

// ======================= edge logits =========================================
__global__ void k_edge_logits(const float* __restrict__ lg, const int* __restrict__ snd,
                              const int* __restrict__ rcv, float* __restrict__ out) {
    int gw   = (blockIdx.x * blockDim.x + threadIdx.x) >> 5;
    int lane = threadIdx.x & 31;
    if (gw >= EE) return;
    const float4* l4 = (const float4*)lg;
    int s = snd[gw], r = rcv[gw];
    float4 a = l4[(size_t)s * 32 + lane];
    float4 b = l4[(size_t)r * 32 + lane];
    float p = a.x * b.x + a.y * b.y + a.z * b.z + a.w * b.w;
#pragma unroll
    for (int o = 16; o > 0; o >>= 1) p += __shfl_down_sync(0xffffffffu, p, o);
    if (lane == 0) out[gw] = p;
}

// ======================= fused value head (one kernel) =======================
// 32 blocks x 32 graphs. Reduce + 5 relu-GEMM layers + tanh. All row-local.
#define VAL_SMEM (128*128*4 + 2*32*128*4)   // W (64KB) + v ping-pong (32KB)

__global__ void __launch_bounds__(256)
k_value(const float* __restrict__ h, const float* __restrict__ ew,
        const float* __restrict__ eb, const float* __restrict__ wo,
        const float* __restrict__ bo, float* __restrict__ out) {
    extern __shared__ __align__(16) float vsm[];
    float* Ws  = vsm;                // 16384 floats
    float* vb0 = vsm + 16384;        // 4096
    float* vb1 = vb0 + 4096;         // 4096
    int tid = threadIdx.x;
    int g0 = blockIdx.x * 32;

    // phase 0: v = mean over local rows 1..63
    for (int idx = tid; idx < 32 * 128; idx += 256) {
        int g = idx >> 7, col = idx & 127;
        const float* hp = h + ((size_t)(g0 + g) * 64 + 1) * 128 + col;
        float acc = 0.f;
        for (int j = 0; j < 63; j++) acc += hp[j * 128];
        vb0[idx] = acc * (1.f / 63.f);
    }

    float* cur = vb0;
    float* nxt = vb1;
    for (int layer = 0; layer < 5; layer++) {
        __syncthreads();
        for (int idx = tid; idx < 128 * 32; idx += 256)
            ((float4*)Ws)[idx] = ((const float4*)(ew + (size_t)layer * 16384))[idx];
        __syncthreads();
        for (int idx = tid; idx < 32 * 32; idx += 256) {
            int g = idx >> 5, cg = (idx & 31) * 4;
            const float* vr = &cur[g * 128];
            float4 acc = *(const float4*)&eb[layer * 128 + cg];
            for (int k = 0; k < 128; k++) {
                float av = vr[k];
                float4 w = *(const float4*)&Ws[k * 128 + cg];
                acc.x = fmaf(av, w.x, acc.x);
                acc.y = fmaf(av, w.y, acc.y);
                acc.z = fmaf(av, w.z, acc.z);
                acc.w = fmaf(av, w.w, acc.w);
            }
            acc.x = fmaxf(acc.x, 0.f); acc.y = fmaxf(acc.y, 0.f);
            acc.z = fmaxf(acc.z, 0.f); acc.w = fmaxf(acc.w, 0.f);
            *(float4*)&nxt[g * 128 + cg] = acc;
        }
        float* t = cur; cur = nxt; nxt = t;
    }
    __syncthreads();

    // tanh(v @ wo + bo): warp per 4 graphs
    int w = tid >> 5, l = tid & 31;
    for (int sub = 0; sub < 4; sub++) {
        int g = w * 4 + sub;
        const float* vr = &cur[g * 128];
        float p = vr[l] * wo[l] + vr[l + 32] * wo[l + 32] +
                  vr[l + 64] * wo[l + 64] + vr[l + 96] * wo[l + 96];
#pragma unroll
        for (int o = 16; o > 0; o >>= 1) p += __shfl_down_sync(0xffffffffu, p, o);
        if (l == 0) out[EE + g0 + g] = tanhf(p + bo[0]);
    }
}

// ======================= host launcher =======================================
extern "C" void kernel_launch(void* const* d_in, const int* in_sizes, int n_in,
                              void* d_out, int out_size) {
    const int*   nodes = (const int*)d_in[0];
    const int*   snd   = (const int*)d_in[1];
    const int*   rcv   = (const int*)d_in[2];
    const int*   gsnd  = (const int*)d_in[3];
    const int*   grcv  = (const int*)d_in[4];
    const float* embed = (const float*)d_in[6];
    const float* w1    = (const float*)d_in[7];
    const float* b1    = (const float*)d_in[8];
    const float* w2    = (const float*)d_in[9];
    const float* b2    = (const float*)d_in[10];
    const float* w3    = (const float*)d_in[11];
    const float* b3    = (const float*)d_in[12];
    const float* wl    = (const float*)d_in[13];
    const float* bl    = (const float*)d_in[14];
    const float* ew    = (const float*)d_in[15];
    const float* eb    = (const float*)d_in[16];
    const float* wo    = (const float*)d_in[17];
    const float* bo    = (const float*)d_in[18];
    float* out = (float*)d_out;

    float *h, *lg, *s1, *r1, *c1, *s2, *r2, *c2;
    __nv_bfloat16 *mHi, *mLo, *gHi, *gLo;
    __nv_bfloat16 *wt1h, *wt1l, *wt2h, *wt2l, *wt3h, *wt3l, *wtlh, *wtll;
    cudaGetSymbolAddress((void**)&h,    d_h);
    cudaGetSymbolAddress((void**)&lg,   d_lg);
    cudaGetSymbolAddress((void**)&mHi,  d_mHi);
    cudaGetSymbolAddress((void**)&mLo,  d_mLo);
    cudaGetSymbolAddress((void**)&gHi,  d_gHi);
    cudaGetSymbolAddress((void**)&gLo,  d_gLo);
    cudaGetSymbolAddress((void**)&wt1h, d_wt1h);
    cudaGetSymbolAddress((void**)&wt1l, d_wt1l);
    cudaGetSymbolAddress((void**)&wt2h, d_wt2h);
    cudaGetSymbolAddress((void**)&wt2l, d_wt2l);
    cudaGetSymbolAddress((void**)&wt3h, d_wt3h);
    cudaGetSymbolAddress((void**)&wt3l, d_wt3l);
    cudaGetSymbolAddress((void**)&wtlh, d_wtlh);
    cudaGetSymbolAddress((void**)&wtll, d_wtll);
    cudaGetSymbolAddress((void**)&s1,   d_s1);
    cudaGetSymbolAddress((void**)&r1,   d_r1);
    cudaGetSymbolAddress((void**)&c1,   d_c1);
    cudaGetSymbolAddress((void**)&s2,   d_s2);
    cudaGetSymbolAddress((void**)&r2,   d_r2);
    cudaGetSymbolAddress((void**)&c2,   d_c2);

    cudaFuncSetAttribute(k_mmaS, cudaFuncAttributeMaxDynamicSharedMemorySize, SM_TOTAL);
    cudaFuncSetAttribute(k_mmaD, cudaFuncAttributeMaxDynamicSharedMemorySize, SM_TOTAL);
    cudaFuncSetAttribute(k_value, cudaFuncAttributeMaxDynamicSharedMemorySize, VAL_SMEM);

    // ---- weight conversion + counter zero, embed ----
    k_wt_all<<<(WT_TOTAL + 255) / 256, 256>>>(w1, w2, w3, wl);
    k_embed<<<(NN * 32 + 255) / 256, 256>>>(nodes, embed, h);

    // ---- degree / CSR precompute (layer-invariant) ----
    k_histB<<<(EE + EEG + 255) / 256, 256>>>(snd, rcv, gsnd, grcv);
    k_scanB<<<2, 1024>>>();
    k_scatB<<<(EE + EEG + 255) / 256, 256>>>(snd, rcv, gsnd, grcv);

    // ---- 7 GNN layers ----
    for (int i = 0; i < 7; i++) {
        k_aggB<<<2 * NN * 32 / 256, 256>>>(h);
        k_mmaD<<<1024, 256, SM_TOTAL>>>(
            mHi, mLo, wt1h + (size_t)i * 16384, wt1l + (size_t)i * 16384,
            b1 + i * 128, c1, r1, mHi, mLo,
            gHi, gLo, wt2h + (size_t)i * 16384, wt2l + (size_t)i * 16384,
            b2 + i * 128, c2, r2, gHi, gLo);
        int last = (i == 6);
        k_mmaS<<<512, 256, SM_TOTAL>>>(mHi, mLo, gHi, gLo,
                                       wt3h + (size_t)i * 32768, wt3l + (size_t)i * 32768,
                                       256, b3 + i * 128, nullptr, nullptr, 1,
                                       h, last ? mHi : nullptr, last ? mLo : nullptr);
    }

    // ---- policy head ----
    k_mmaS<<<512, 256, SM_TOTAL>>>(mHi, mLo, nullptr, nullptr, wtlh, wtll,
                                   128, bl, nullptr, nullptr, 0,
                                   lg, nullptr, nullptr);
    k_edge_logits<<<(EE * 32) / 256, 256>>>(lg, snd, rcv, out);

    // ---- value head (fused) ----
    k_value<<<32, 256, VAL_SMEM>>>(h, ew, eb, wo, bo, out);
}

// round 7
// speedup vs baseline: 1.1986x; 1.1986x over previous
#include <cuda_runtime.h>
#include <cuda_bf16.h>
#include <math.h>
#include <stdint.h>

#define NN   65536
#define BB   1024
#define EE   2097152
#define EEG  524288
#define DIM  128

// ======================= portable PTX helpers ================================
__device__ __forceinline__ uint32_t smem_to_u32(const void* p) {
    uint32_t a;
    asm("{ .reg .u64 t; cvta.to.shared.u64 t, %1; cvt.u32.u64 %0, t; }" : "=r"(a) : "l"(p));
    return a;
}

__device__ __forceinline__ void ldsm4(uint32_t* r, uint32_t addr) {
    asm volatile("ldmatrix.sync.aligned.m8n8.x4.shared.b16 {%0,%1,%2,%3}, [%4];"
                 : "=r"(r[0]), "=r"(r[1]), "=r"(r[2]), "=r"(r[3]) : "r"(addr));
}

__device__ __forceinline__ void mma16816(float* c, const uint32_t* a, const uint32_t* b) {
    asm volatile("mma.sync.aligned.m16n8k16.row.col.f32.bf16.bf16.f32 "
                 "{%0,%1,%2,%3}, {%4,%5,%6,%7}, {%8,%9}, {%0,%1,%2,%3};"
                 : "+f"(c[0]), "+f"(c[1]), "+f"(c[2]), "+f"(c[3])
                 : "r"(a[0]), "r"(a[1]), "r"(a[2]), "r"(a[3]), "r"(b[0]), "r"(b[1]));
}

__device__ __forceinline__ void cp_async16(uint32_t dst, const void* src) {
    asm volatile("cp.async.cg.shared.global [%0], [%1], 16;" :: "r"(dst), "l"(src) : "memory");
}

// ======================= static scratch ======================================
__device__ float d_h   [(size_t)NN * DIM];   // node features (fp32)
__device__ float d_lg  [(size_t)NN * DIM];   // logit-head features (fp32)

__device__ __nv_bfloat16 d_mHi[(size_t)NN * DIM], d_mLo[(size_t)NN * DIM];
__device__ __nv_bfloat16 d_gHi[(size_t)NN * DIM], d_gLo[(size_t)NN * DIM];

// converted transposed weights (bf16 hi/lo), layout [n][K]
__device__ __nv_bfloat16 d_wt1h[7*128*128], d_wt1l[7*128*128];
__device__ __nv_bfloat16 d_wt2h[7*128*128], d_wt2l[7*128*128];
__device__ __nv_bfloat16 d_wt3h[7*128*256], d_wt3l[7*128*256];
__device__ __nv_bfloat16 d_wtlh[128*128],   d_wtll[128*128];

__device__ int d_csrM[EE];
__device__ int d_csrG[EEG];
__device__ int d_offM[NN + 1];
__device__ int d_offG[NN + 1];
__device__ int d_curM[NN];
__device__ int d_curG[NN];
__device__ int d_cntOutM[NN], d_cntInM[NN], d_cntOutG[NN], d_cntInG[NN];
__device__ float d_s1[NN], d_r1[NN], d_c1[NN];
__device__ float d_s2[NN], d_r2[NN], d_c2[NN];
__device__ int d_psum[512];    // per-block partial sums (256 per edge set)
__device__ int d_pbase[512];   // exclusive bases per block

// ======================= weight convert + counter zero (one launch) ==========
#define WT_S1 (7*16384)
#define WT_S3 (7*32768)
#define WT_TOTAL (2*WT_S1 + WT_S3 + 16384)
__global__ void k_wt_all(const float* __restrict__ w1, const float* __restrict__ w2,
                         const float* __restrict__ w3, const float* __restrict__ wl) {
    int id = blockIdx.x * blockDim.x + threadIdx.x;
    if (id < NN) { d_cntOutM[id] = 0; d_cntInM[id] = 0; d_cntOutG[id] = 0; d_cntInG[id] = 0; }
    float v;
    __nv_bfloat16 *hi, *lo;
    int oidx;
    if (id < WT_S1) {
        int layer = id >> 14, w = id & 16383;
        int n = w >> 7, k = w & 127;
        v = w1[(size_t)(layer << 14) + k * 128 + n];
        hi = d_wt1h; lo = d_wt1l; oidx = (layer << 14) + n * 128 + k;
    } else if (id < 2 * WT_S1) {
        int id2 = id - WT_S1;
        int layer = id2 >> 14, w = id2 & 16383;
        int n = w >> 7, k = w & 127;
        v = w2[(size_t)(layer << 14) + k * 128 + n];
        hi = d_wt2h; lo = d_wt2l; oidx = (layer << 14) + n * 128 + k;
    } else if (id < 2 * WT_S1 + WT_S3) {
        int id3 = id - 2 * WT_S1;
        int layer = id3 >> 15, w = id3 & 32767;
        int n = w >> 8, k = w & 255;
        v = w3[(size_t)(layer << 15) + k * 128 + n];
        hi = d_wt3h; lo = d_wt3l; oidx = (layer << 15) + n * 256 + k;
    } else if (id < WT_TOTAL) {
        int id4 = id - (2 * WT_S1 + WT_S3);
        int n = id4 >> 7, k = id4 & 127;
        v = wl[k * 128 + n];
        hi = d_wtlh; lo = d_wtll; oidx = n * 128 + k;
    } else return;
    __nv_bfloat16 h = __float2bfloat16(v);
    hi[oidx] = h;
    lo[oidx] = __float2bfloat16(v - __bfloat162float(h));
}

// ======================= precompute ==========================================
__global__ void k_histB(const int* __restrict__ snd, const int* __restrict__ rcv,
                        const int* __restrict__ gsnd, const int* __restrict__ grcv) {
    int e = blockIdx.x * blockDim.x + threadIdx.x;
    if (e < EE) {
        atomicAdd(&d_cntOutM[snd[e]], 1); atomicAdd(&d_cntInM[rcv[e]], 1);
    } else if (e < EE + EEG) {
        int g = e - EE;
        atomicAdd(&d_cntOutG[gsnd[g]], 1); atomicAdd(&d_cntInG[grcv[g]], 1);
    }
}

// --- multi-block scan phase A: block partial sums + norms (fully parallel) ---
__global__ void k_scanA() {
    int set = blockIdx.x >> 8;
    int t = threadIdx.x;
    int i = (blockIdx.x & 255) * 256 + t;
    const int* cnt  = set ? d_cntInG  : d_cntInM;
    const int* cntO = set ? d_cntOutG : d_cntOutM;
    float* sA = set ? d_s2 : d_s1;
    float* cA = set ? d_c2 : d_c1;
    float* rA = set ? d_r2 : d_r1;
    int cv = cnt[i];
    float sv = rsqrtf((float)(cntO[i] + 1));
    sA[i] = sv;
    cA[i] = sv;                                  // self-edge term; scatter adds rest
    rA[i] = rsqrtf((float)(cv + 1));
    __shared__ int red[256];
    red[t] = cv;
    __syncthreads();
    for (int d = 128; d > 0; d >>= 1) {
        if (t < d) red[t] += red[t + d];
        __syncthreads();
    }
    if (t == 0) d_psum[blockIdx.x] = red[0];
}

// --- phase B: scan 256 block partials per set (2 blocks) ---
__global__ void k_scanM() {
    int set = blockIdx.x;
    int t = threadIdx.x;
    __shared__ int ps[256];
    int v = d_psum[set * 256 + t];
    ps[t] = v;
    __syncthreads();
    for (int d = 1; d < 256; d <<= 1) {
        int x = 0;
        if (t >= d) x = ps[t - d];
        __syncthreads();
        ps[t] += x;
        __syncthreads();
    }
    d_pbase[set * 256 + t] = ps[t] - v;          // exclusive base
    if (t == 255) {
        int* off = set ? d_offG : d_offM;
        off[NN] = ps[255];
    }
}

// --- phase C: per-block exclusive scan + base -> offsets ---
__global__ void k_scanC() {
    int set = blockIdx.x >> 8;
    int b = blockIdx.x & 255;
    int t = threadIdx.x;
    int i = b * 256 + t;
    const int* cnt = set ? d_cntInG : d_cntInM;
    int* off = set ? d_offG : d_offM;
    int* cur = set ? d_curG : d_curM;
    __shared__ int ps[256];
    int v = cnt[i];
    ps[t] = v;
    __syncthreads();
    for (int d = 1; d < 256; d <<= 1) {
        int x = 0;
        if (t >= d) x = ps[t - d];
        __syncthreads();
        ps[t] += x;
        __syncthreads();
    }
    int excl = ps[t] - v + d_pbase[set * 256 + b];
    off[i] = excl;
    cur[i] = excl;
}

// scatter both edge sets + fold in csum (c[r] += s[snd]) via float atomics
__global__ void k_scatB(const int* __restrict__ snd, const int* __restrict__ rcv,
                        const int* __restrict__ gsnd, const int* __restrict__ grcv) {
    int e = blockIdx.x * blockDim.x + threadIdx.x;
    if (e < EE) {
        int s = snd[e], r = rcv[e];
        int p = atomicAdd(&d_curM[r], 1);
        d_csrM[p] = s;
        atomicAdd(&d_c1[r], d_s1[s]);
    } else if (e < EE + EEG) {
        int g = e - EE;
        int s = gsnd[g], r = grcv[g];
        int p = atomicAdd(&d_curG[r], 1);
        d_csrG[p] = s;
        atomicAdd(&d_c2[r], d_s2[s]);
    }
}

// ======================= embedding ==========================================
__global__ void k_embed(const int* __restrict__ nodes, const float* __restrict__ embed,
                        float* __restrict__ h) {
    int i = blockIdx.x * blockDim.x + threadIdx.x;
    if (i < NN * 32) {
        int node = i >> 5;
        int c    = i & 31;
        ((float4*)h)[i] = ((const float4*)embed)[nodes[node] * 32 + c];
    }
}

// ======================= pull aggregation (unroll-4 prefetch) ================
__global__ void k_aggB(const float* __restrict__ h) {
    int gw   = (blockIdx.x * blockDim.x + threadIdx.x) >> 5;  // 0 .. 2*NN-1
    int lane = threadIdx.x & 31;
    int isG  = gw >= NN;
    int node = gw - (isG ? NN : 0);
    if (gw >= 2 * NN) return;
    const int* off = isG ? d_offG : d_offM;
    const int* csr = isG ? d_csrG : d_csrM;
    const float* sn = isG ? d_s2 : d_s1;
    __nv_bfloat16* oHi = isG ? d_gHi : d_mHi;
    __nv_bfloat16* oLo = isG ? d_gLo : d_mLo;

    const float4* h4 = (const float4*)h;
    float s0 = sn[node];
    float4 a = h4[(size_t)node * 32 + lane];
    float4 acc;
    acc.x = a.x * s0; acc.y = a.y * s0; acc.z = a.z * s0; acc.w = a.w * s0;
    int e  = off[node];
    int e1 = off[node + 1];
    for (; e + 4 <= e1; e += 4) {
        int i0 = csr[e], i1 = csr[e + 1], i2 = csr[e + 2], i3 = csr[e + 3];
        float c0 = sn[i0], c1 = sn[i1], c2 = sn[i2], c3 = sn[i3];
        float4 v0 = h4[(size_t)i0 * 32 + lane];
        float4 v1 = h4[(size_t)i1 * 32 + lane];
        float4 v2 = h4[(size_t)i2 * 32 + lane];
        float4 v3 = h4[(size_t)i3 * 32 + lane];
        acc.x = fmaf(v0.x, c0, acc.x); acc.y = fmaf(v0.y, c0, acc.y);
        acc.z = fmaf(v0.z, c0, acc.z); acc.w = fmaf(v0.w, c0, acc.w);
        acc.x = fmaf(v1.x, c1, acc.x); acc.y = fmaf(v1.y, c1, acc.y);
        acc.z = fmaf(v1.z, c1, acc.z); acc.w = fmaf(v1.w, c1, acc.w);
        acc.x = fmaf(v2.x, c2, acc.x); acc.y = fmaf(v2.y, c2, acc.y);
        acc.z = fmaf(v2.z, c2, acc.z); acc.w = fmaf(v2.w, c2, acc.w);
        acc.x = fmaf(v3.x, c3, acc.x); acc.y = fmaf(v3.y, c3, acc.y);
        acc.z = fmaf(v3.z, c3, acc.z); acc.w = fmaf(v3.w, c3, acc.w);
    }
    for (; e < e1; e++) {
        int   s  = csr[e];
        float sc = sn[s];
        float4 v = h4[(size_t)s * 32 + lane];
        acc.x = fmaf(v.x, sc, acc.x);
        acc.y = fmaf(v.y, sc, acc.y);
        acc.z = fmaf(v.z, sc, acc.z);
        acc.w = fmaf(v.w, sc, acc.w);
    }
    __nv_bfloat16 hv[4], lv[4];
    float av[4] = {acc.x, acc.y, acc.z, acc.w};
#pragma unroll
    for (int j = 0; j < 4; j++) {
        hv[j] = __float2bfloat16(av[j]);
        lv[j] = __float2bfloat16(av[j] - __bfloat162float(hv[j]));
    }
    size_t p = (size_t)node * 128 + lane * 4;
    *(uint2*)&oHi[p] = *(uint2*)hv;
    *(uint2*)&oLo[p] = *(uint2*)lv;
}

// ======================= HMMA GEMM (cp.async double-buffered) ================
#define SLICE_BYTES 65536
#define SM_TOTAL    131072

__device__ __forceinline__ void stage_slice(
    uint32_t sbuf,
    const __nv_bfloat16* Ah, const __nv_bfloat16* Al,
    const __nv_bfloat16* wtHi, const __nv_bfloat16* wtLo,
    int rowBase, int K, int c, int ks, int tid) {
#pragma unroll
    for (int j = 0; j < 16; j++) {
        int tile = j >> 2;
        int cidx = tid + (j & 3) * 256;
        int r = cidx >> 3, ch = cidx & 7;
        uint32_t dst = sbuf + tile * 16384 + (uint32_t)r * 128 +
                       (uint32_t)((ch * 16) ^ ((r & 7) << 4));
        const __nv_bfloat16* src;
        if (tile == 0)      src = Ah   + (size_t)(rowBase + r) * 128 + ks * 64 + ch * 8;
        else if (tile == 1) src = Al   + (size_t)(rowBase + r) * 128 + ks * 64 + ch * 8;
        else if (tile == 2) src = wtHi + (size_t)r * K + c * 128 + ks * 64 + ch * 8;
        else                src = wtLo + (size_t)r * K + c * 128 + ks * 64 + ch * 8;
        cp_async16(dst, src);
    }
    asm volatile("cp.async.commit_group;" ::: "memory");
}

__device__ __forceinline__ void mma_compute_slice(
    uint32_t base, int ra_base, uint32_t kxA, uint32_t xorA,
    int rb_base, uint32_t kxB, uint32_t xorB, float acc[16][4]) {
#pragma unroll
    for (int ka = 0; ka < 4; ka++) {
        uint32_t fAh[2][4], fAl[2][4];
#pragma unroll
        for (int ma = 0; ma < 2; ma++) {
            uint32_t off = (uint32_t)(ra_base + ma * 16) * 128 +
                           (((uint32_t)(ka * 32) + kxA) ^ xorA);
            ldsm4(fAh[ma], base + off);
            ldsm4(fAl[ma], base + 16384 + off);
        }
#pragma unroll
        for (int nb = 0; nb < 4; nb++) {
            uint32_t off = (uint32_t)(rb_base + nb * 16) * 128 +
                           (((uint32_t)(ka * 32) + kxB) ^ xorB);
            uint32_t wh[4], wl[4];
            ldsm4(wh, base + 32768 + off);
            ldsm4(wl, base + 49152 + off);
#pragma unroll
            for (int ma = 0; ma < 2; ma++) {
                float* a0 = acc[ma * 8 + nb * 2];
                float* a1 = acc[ma * 8 + nb * 2 + 1];
                mma16816(a0, fAh[ma], wh);
                mma16816(a1, fAh[ma], wh + 2);
                mma16816(a0, fAl[ma], wh);
                mma16816(a1, fAl[ma], wh + 2);
                mma16816(a0, fAh[ma], wl);
                mma16816(a1, fAh[ma], wl + 2);
            }
        }
    }
}

__device__ __forceinline__ void mma_body(
    const __nv_bfloat16* aHi, const __nv_bfloat16* aLo,
    const __nv_bfloat16* gHi, const __nv_bfloat16* gLo,
    const __nv_bfloat16* wtHi, const __nv_bfloat16* wtLo,
    int K, const float* bias, const float* crow, const float* rrow,
    int relu, float* outF, __nv_bfloat16* outHi, __nv_bfloat16* outLo,
    int rowBase, char* smem) {
    uint32_t sb = smem_to_u32(smem);
    int tid = threadIdx.x;
    int wid = tid >> 5;
    int l   = tid & 31;
    int m0 = (wid >> 1) * 32;
    int n0 = (wid & 1) * 64;

    int ra_base = m0 + (l & 7) + ((l >> 3) & 1) * 8;
    uint32_t kxA = ((l >> 4) & 1) * 16;
    uint32_t xorA = (uint32_t)((ra_base & 7) << 4);
    int rb_base = n0 + (l & 7) + ((l >> 4) & 1) * 8;
    uint32_t kxB = ((l >> 3) & 1) * 16;
    uint32_t xorB = (uint32_t)((rb_base & 7) << 4);

    float acc[16][4];
#pragma unroll
    for (int i = 0; i < 16; i++)
#pragma unroll
        for (int j = 0; j < 4; j++) acc[i][j] = 0.f;

    int nslices = K >> 6;
    stage_slice(sb, aHi, aLo, wtHi, wtLo, rowBase, K, 0, 0, tid);
    for (int s = 0; s < nslices; s++) {
        if (s + 1 < nslices) {
            int c = (s + 1) >> 1, ks = (s + 1) & 1;
            stage_slice(sb + ((s + 1) & 1) * SLICE_BYTES,
                        c ? gHi : aHi, c ? gLo : aLo, wtHi, wtLo,
                        rowBase, K, c, ks, tid);
            asm volatile("cp.async.wait_group 1;" ::: "memory");
        } else {
            asm volatile("cp.async.wait_group 0;" ::: "memory");
        }
        __syncthreads();
        mma_compute_slice(sb + (s & 1) * SLICE_BYTES,
                          ra_base, kxA, xorA, rb_base, kxB, xorB, acc);
        __syncthreads();
    }

    int gid = l >> 2, tig = l & 3;
#pragma unroll
    for (int ma = 0; ma < 2; ma++) {
        int r0 = rowBase + m0 + ma * 16 + gid;
        int r1 = r0 + 8;
        float cm0 = crow ? crow[r0] : 1.f, rm0 = rrow ? rrow[r0] : 1.f;
        float cm1 = crow ? crow[r1] : 1.f, rm1 = rrow ? rrow[r1] : 1.f;
#pragma unroll
        for (int na = 0; na < 8; na++) {
            int col = n0 + na * 8 + tig * 2;
            float b0 = bias[col], b1 = bias[col + 1];
            float* ac = acc[ma * 8 + na];
            float o00 = (ac[0] + b0 * cm0) * rm0;
            float o01 = (ac[1] + b1 * cm0) * rm0;
            float o10 = (ac[2] + b0 * cm1) * rm1;
            float o11 = (ac[3] + b1 * cm1) * rm1;
            if (relu) {
                o00 = fmaxf(o00, 0.f); o01 = fmaxf(o01, 0.f);
                o10 = fmaxf(o10, 0.f); o11 = fmaxf(o11, 0.f);
            }
            if (outF) {
                *(float2*)&outF[(size_t)r0 * 128 + col] = make_float2(o00, o01);
                *(float2*)&outF[(size_t)r1 * 128 + col] = make_float2(o10, o11);
            }
            if (outHi) {
                __nv_bfloat16 h00 = __float2bfloat16(o00), h01 = __float2bfloat16(o01);
                __nv_bfloat16 h10 = __float2bfloat16(o10), h11 = __float2bfloat16(o11);
                __nv_bfloat162 hp0; hp0.x = h00; hp0.y = h01;
                __nv_bfloat162 hp1; hp1.x = h10; hp1.y = h11;
                __nv_bfloat162 lp0;
                lp0.x = __float2bfloat16(o00 - __bfloat162float(h00));
                lp0.y = __float2bfloat16(o01 - __bfloat162float(h01));
                __nv_bfloat162 lp1;
                lp1.x = __float2bfloat16(o10 - __bfloat162float(h10));
                lp1.y = __float2bfloat16(o11 - __bfloat162float(h11));
                *(__nv_bfloat162*)&outHi[(size_t)r0 * 128 + col] = hp0;
                *(__nv_bfloat162*)&outHi[(size_t)r1 * 128 + col] = hp1;
                *(__nv_bfloat162*)&outLo[(size_t)r0 * 128 + col] = lp0;
                *(__nv_bfloat162*)&outLo[(size_t)r1 * 128 + col] = lp1;
            }
        }
    }
}

__global__ void __launch_bounds__(256)
k_mmaS(const __nv_bfloat16* aHi, const __nv_bfloat16* aLo,
       const __nv_bfloat16* gHi, const __nv_bfloat16* gLo,
       const __nv_bfloat16* wtHi, const __nv_bfloat16* wtLo,
       int K, const float* bias, const float* crow, const float* rrow,
       int relu, float* outF, __nv_bfloat16* outHi, __nv_bfloat16* outLo) {
    extern __shared__ __align__(16) char smem[];
    mma_body(aHi, aLo, gHi, gLo, wtHi, wtLo, K, bias, crow, rrow,
             relu, outF, outHi, outLo, blockIdx.x * 128, smem);
}

__global__ void __launch_bounds__(256)
k_mmaD(const __nv_bfloat16* a1Hi, const __nv_bfloat16* a1Lo,
       const __nv_bfloat16* wt1Hi, const __nv_bfloat16* wt1Lo,
       const float* bias1, const float* crow1, const float* rrow1,
       __nv_bfloat16* out1Hi, __nv_bfloat16* out1Lo,
       const __nv_bfloat16* a2Hi, const __nv_bfloat16* a2Lo,
       const __nv_bfloat16* wt2Hi, const __nv_bfloat16* wt2Lo,
       const float* bias2, const float* crow2, const float* rrow2,
       __nv_bfloat16* out2Hi, __nv_bfloat16* out2Lo) {
    extern __shared__ __align__(16) char smem[];
    if (blockIdx.x < 512)
        mma_body(a1Hi, a1Lo, nullptr, nullptr, wt1Hi, wt1Lo, 128,
                 bias1, crow1, rrow1, 0, nullptr, out1Hi, out1Lo,
                 blockIdx.x * 128, smem);
    else
        mma_body(a2Hi, a2Lo, nullptr, nullptr, wt2Hi, wt2Lo, 128,
                 bias2, crow2, rrow2, 0, nullptr, out2Hi, out2Lo,
                 (blockIdx.x - 512) * 128, smem);
}

// ======================= edge logits =========================================
__global__ void k_edge_logits(const float* __restrict__ lg, const int* __restrict__ snd,
                              const int* __restrict__ rcv, float* __restrict__ out) {
    int gw   = (blockIdx.x * blockDim.x + threadIdx.x) >> 5;
    int lane = threadIdx.x & 31;
    if (gw >= EE) return;
    const float4* l4 = (const float4*)lg;
    int s = snd[gw], r = rcv[gw];
    float4 a = l4[(size_t)s * 32 + lane];
    float4 b = l4[(size_t)r * 32 + lane];
    float p = a.x * b.x + a.y * b.y + a.z * b.z + a.w * b.w;
#pragma unroll
    for (int o = 16; o > 0; o >>= 1) p += __shfl_down_sync(0xffffffffu, p, o);
    if (lane == 0) out[gw] = p;
}

// ======================= fused value head (one kernel) =======================
#define VAL_SMEM (128*128*4 + 2*32*128*4)   // W (64KB) + v ping-pong (32KB)

__global__ void __launch_bounds__(256)
k_value(const float* __restrict__ h, const float* __restrict__ ew,
        const float* __restrict__ eb, const float* __restrict__ wo,
        const float* __restrict__ bo, float* __restrict__ out) {
    extern __shared__ __align__(16) float vsm[];
    float* Ws  = vsm;                // 16384 floats
    float* vb0 = vsm + 16384;        // 4096
    float* vb1 = vb0 + 4096;         // 4096
    int tid = threadIdx.x;
    int g0 = blockIdx.x * 32;

    for (int idx = tid; idx < 32 * 128; idx += 256) {
        int g = idx >> 7, col = idx & 127;
        const float* hp = h + ((size_t)(g0 + g) * 64 + 1) * 128 + col;
        float acc = 0.f;
        for (int j = 0; j < 63; j++) acc += hp[j * 128];
        vb0[idx] = acc * (1.f / 63.f);
    }

    float* cur = vb0;
    float* nxt = vb1;
    for (int layer = 0; layer < 5; layer++) {
        __syncthreads();
        for (int idx = tid; idx < 128 * 32; idx += 256)
            ((float4*)Ws)[idx] = ((const float4*)(ew + (size_t)layer * 16384))[idx];
        __syncthreads();
        for (int idx = tid; idx < 32 * 32; idx += 256) {
            int g = idx >> 5, cg = (idx & 31) * 4;
            const float* vr = &cur[g * 128];
            float4 acc = *(const float4*)&eb[layer * 128 + cg];
            for (int k = 0; k < 128; k++) {
                float av = vr[k];
                float4 w = *(const float4*)&Ws[k * 128 + cg];
                acc.x = fmaf(av, w.x, acc.x);
                acc.y = fmaf(av, w.y, acc.y);
                acc.z = fmaf(av, w.z, acc.z);
                acc.w = fmaf(av, w.w, acc.w);
            }
            acc.x = fmaxf(acc.x, 0.f); acc.y = fmaxf(acc.y, 0.f);
            acc.z = fmaxf(acc.z, 0.f); acc.w = fmaxf(acc.w, 0.f);
            *(float4*)&nxt[g * 128 + cg] = acc;
        }
        float* t = cur; cur = nxt; nxt = t;
    }
    __syncthreads();

    int w = tid >> 5, l = tid & 31;
    for (int sub = 0; sub < 4; sub++) {
        int g = w * 4 + sub;
        const float* vr = &cur[g * 128];
        float p = vr[l] * wo[l] + vr[l + 32] * wo[l + 32] +
                  vr[l + 64] * wo[l + 64] + vr[l + 96] * wo[l + 96];
#pragma unroll
        for (int o = 16; o > 0; o >>= 1) p += __shfl_down_sync(0xffffffffu, p, o);
        if (l == 0) out[EE + g0 + g] = tanhf(p + bo[0]);
    }
}

// ======================= host launcher =======================================
extern "C" void kernel_launch(void* const* d_in, const int* in_sizes, int n_in,
                              void* d_out, int out_size) {
    const int*   nodes = (const int*)d_in[0];
    const int*   snd   = (const int*)d_in[1];
    const int*   rcv   = (const int*)d_in[2];
    const int*   gsnd  = (const int*)d_in[3];
    const int*   grcv  = (const int*)d_in[4];
    const float* embed = (const float*)d_in[6];
    const float* w1    = (const float*)d_in[7];
    const float* b1    = (const float*)d_in[8];
    const float* w2    = (const float*)d_in[9];
    const float* b2    = (const float*)d_in[10];
    const float* w3    = (const float*)d_in[11];
    const float* b3    = (const float*)d_in[12];
    const float* wl    = (const float*)d_in[13];
    const float* bl    = (const float*)d_in[14];
    const float* ew    = (const float*)d_in[15];
    const float* eb    = (const float*)d_in[16];
    const float* wo    = (const float*)d_in[17];
    const float* bo    = (const float*)d_in[18];
    float* out = (float*)d_out;

    float *h, *lg, *s1, *r1, *c1, *s2, *r2, *c2;
    __nv_bfloat16 *mHi, *mLo, *gHi, *gLo;
    __nv_bfloat16 *wt1h, *wt1l, *wt2h, *wt2l, *wt3h, *wt3l, *wtlh, *wtll;
    cudaGetSymbolAddress((void**)&h,    d_h);
    cudaGetSymbolAddress((void**)&lg,   d_lg);
    cudaGetSymbolAddress((void**)&mHi,  d_mHi);
    cudaGetSymbolAddress((void**)&mLo,  d_mLo);
    cudaGetSymbolAddress((void**)&gHi,  d_gHi);
    cudaGetSymbolAddress((void**)&gLo,  d_gLo);
    cudaGetSymbolAddress((void**)&wt1h, d_wt1h);
    cudaGetSymbolAddress((void**)&wt1l, d_wt1l);
    cudaGetSymbolAddress((void**)&wt2h, d_wt2h);
    cudaGetSymbolAddress((void**)&wt2l, d_wt2l);
    cudaGetSymbolAddress((void**)&wt3h, d_wt3h);
    cudaGetSymbolAddress((void**)&wt3l, d_wt3l);
    cudaGetSymbolAddress((void**)&wtlh, d_wtlh);
    cudaGetSymbolAddress((void**)&wtll, d_wtll);
    cudaGetSymbolAddress((void**)&s1,   d_s1);
    cudaGetSymbolAddress((void**)&r1,   d_r1);
    cudaGetSymbolAddress((void**)&c1,   d_c1);
    cudaGetSymbolAddress((void**)&s2,   d_s2);
    cudaGetSymbolAddress((void**)&r2,   d_r2);
    cudaGetSymbolAddress((void**)&c2,   d_c2);

    cudaFuncSetAttribute(k_mmaS, cudaFuncAttributeMaxDynamicSharedMemorySize, SM_TOTAL);
    cudaFuncSetAttribute(k_mmaD, cudaFuncAttributeMaxDynamicSharedMemorySize, SM_TOTAL);
    cudaFuncSetAttribute(k_value, cudaFuncAttributeMaxDynamicSharedMemorySize, VAL_SMEM);

    // ---- weight conversion + counter zero, embed ----
    k_wt_all<<<(WT_TOTAL + 255) / 256, 256>>>(w1, w2, w3, wl);
    k_embed<<<(NN * 32 + 255) / 256, 256>>>(nodes, embed, h);

    // ---- degree / CSR precompute (layer-invariant, parallel scan) ----
    k_histB<<<(EE + EEG + 255) / 256, 256>>>(snd, rcv, gsnd, grcv);
    k_scanA<<<512, 256>>>();
    k_scanM<<<2, 256>>>();
    k_scanC<<<512, 256>>>();
    k_scatB<<<(EE + EEG + 255) / 256, 256>>>(snd, rcv, gsnd, grcv);

    // ---- 7 GNN layers ----
    for (int i = 0; i < 7; i++) {
        k_aggB<<<2 * NN * 32 / 256, 256>>>(h);
        k_mmaD<<<1024, 256, SM_TOTAL>>>(
            mHi, mLo, wt1h + (size_t)i * 16384, wt1l + (size_t)i * 16384,
            b1 + i * 128, c1, r1, mHi, mLo,
            gHi, gLo, wt2h + (size_t)i * 16384, wt2l + (size_t)i * 16384,
            b2 + i * 128, c2, r2, gHi, gLo);
        int last = (i == 6);
        k_mmaS<<<512, 256, SM_TOTAL>>>(mHi, mLo, gHi, gLo,
                                       wt3h + (size_t)i * 32768, wt3l + (size_t)i * 32768,
                                       256, b3 + i * 128, nullptr, nullptr, 1,
                                       h, last ? mHi : nullptr, last ? mLo : nullptr);
    }

    // ---- policy head ----
    k_mmaS<<<512, 256, SM_TOTAL>>>(mHi, mLo, nullptr, nullptr, wtlh, wtll,
                                   128, bl, nullptr, nullptr, 0,
                                   lg, nullptr, nullptr);
    k_edge_logits<<<(EE * 32) / 256, 256>>>(lg, snd, rcv, out);

    // ---- value head (fused) ----
    k_value<<<32, 256, VAL_SMEM>>>(h, ew, eb, wo, bo, out);
}

// round 8
// speedup vs baseline: 1.2578x; 1.0494x over previous
#include <cuda_runtime.h>
#include <cuda_bf16.h>
#include <cuda_fp16.h>
#include <math.h>
#include <stdint.h>

#define NN   65536
#define BB   1024
#define EE   2097152
#define EEG  524288
#define DIM  128

// ======================= portable PTX helpers ================================
__device__ __forceinline__ uint32_t smem_to_u32(const void* p) {
    uint32_t a;
    asm("{ .reg .u64 t; cvta.to.shared.u64 t, %1; cvt.u32.u64 %0, t; }" : "=r"(a) : "l"(p));
    return a;
}

__device__ __forceinline__ void ldsm4(uint32_t* r, uint32_t addr) {
    asm volatile("ldmatrix.sync.aligned.m8n8.x4.shared.b16 {%0,%1,%2,%3}, [%4];"
                 : "=r"(r[0]), "=r"(r[1]), "=r"(r[2]), "=r"(r[3]) : "r"(addr));
}

__device__ __forceinline__ void mma16816(float* c, const uint32_t* a, const uint32_t* b) {
    asm volatile("mma.sync.aligned.m16n8k16.row.col.f32.bf16.bf16.f32 "
                 "{%0,%1,%2,%3}, {%4,%5,%6,%7}, {%8,%9}, {%0,%1,%2,%3};"
                 : "+f"(c[0]), "+f"(c[1]), "+f"(c[2]), "+f"(c[3])
                 : "r"(a[0]), "r"(a[1]), "r"(a[2]), "r"(a[3]), "r"(b[0]), "r"(b[1]));
}

__device__ __forceinline__ void cp_async16(uint32_t dst, const void* src) {
    asm volatile("cp.async.cg.shared.global [%0], [%1], 16;" :: "r"(dst), "l"(src) : "memory");
}

// ======================= static scratch ======================================
__device__ float  d_h  [(size_t)NN * DIM];   // node features fp32 (last layer only; value head)
__device__ __half d_h16[(size_t)NN * DIM];   // node features fp16 (aggregation gather source)
__device__ float  d_lg [(size_t)NN * DIM];   // logit-head features (fp32)

__device__ __nv_bfloat16 d_mHi[(size_t)NN * DIM], d_mLo[(size_t)NN * DIM];
__device__ __nv_bfloat16 d_gHi[(size_t)NN * DIM], d_gLo[(size_t)NN * DIM];

// converted transposed weights (bf16 hi/lo), layout [n][K]
__device__ __nv_bfloat16 d_wt1h[7*128*128], d_wt1l[7*128*128];
__device__ __nv_bfloat16 d_wt2h[7*128*128], d_wt2l[7*128*128];
__device__ __nv_bfloat16 d_wt3h[7*128*256], d_wt3l[7*128*256];
__device__ __nv_bfloat16 d_wtlh[128*128],   d_wtll[128*128];

__device__ int d_csrM[EE];
__device__ int d_csrG[EEG];
__device__ int d_offM[NN + 1];
__device__ int d_offG[NN + 1];
__device__ int d_curM[NN];
__device__ int d_curG[NN];
__device__ int d_cntOutM[NN], d_cntInM[NN], d_cntOutG[NN], d_cntInG[NN];
__device__ float d_s1[NN], d_r1[NN], d_c1[NN];
__device__ float d_s2[NN], d_r2[NN], d_c2[NN];
__device__ int d_psum[512];
__device__ int d_pbase[512];

// ======== weight convert + counter zero + embed->fp16 (one launch) ==========
#define WT_S1 (7*16384)
#define WT_S3 (7*32768)
#define WT_TOTAL (2*WT_S1 + WT_S3 + 16384)
#define ALL_TOTAL (WT_TOTAL + NN*16)
__global__ void k_wt_all(const float* __restrict__ w1, const float* __restrict__ w2,
                         const float* __restrict__ w3, const float* __restrict__ wl,
                         const int* __restrict__ nodes, const float* __restrict__ embed) {
    int id = blockIdx.x * blockDim.x + threadIdx.x;
    if (id < NN) { d_cntOutM[id] = 0; d_cntInM[id] = 0; d_cntOutG[id] = 0; d_cntInG[id] = 0; }
    float v;
    __nv_bfloat16 *hi, *lo;
    int oidx;
    if (id < WT_S1) {
        int layer = id >> 14, w = id & 16383;
        int n = w >> 7, k = w & 127;
        v = w1[(size_t)(layer << 14) + k * 128 + n];
        hi = d_wt1h; lo = d_wt1l; oidx = (layer << 14) + n * 128 + k;
    } else if (id < 2 * WT_S1) {
        int id2 = id - WT_S1;
        int layer = id2 >> 14, w = id2 & 16383;
        int n = w >> 7, k = w & 127;
        v = w2[(size_t)(layer << 14) + k * 128 + n];
        hi = d_wt2h; lo = d_wt2l; oidx = (layer << 14) + n * 128 + k;
    } else if (id < 2 * WT_S1 + WT_S3) {
        int id3 = id - 2 * WT_S1;
        int layer = id3 >> 15, w = id3 & 32767;
        int n = w >> 8, k = w & 255;
        v = w3[(size_t)(layer << 15) + k * 128 + n];
        hi = d_wt3h; lo = d_wt3l; oidx = (layer << 15) + n * 256 + k;
    } else if (id < WT_TOTAL) {
        int id4 = id - (2 * WT_S1 + WT_S3);
        int n = id4 >> 7, k = id4 & 127;
        v = wl[k * 128 + n];
        hi = d_wtlh; lo = d_wtll; oidx = n * 128 + k;
    } else if (id < ALL_TOTAL) {
        // embedding lookup -> fp16 h
        int e = id - WT_TOTAL;
        int node = e >> 4, seg = e & 15;
        const float* er = embed + (size_t)nodes[node] * 128 + seg * 8;
        __half hh[8];
#pragma unroll
        for (int j = 0; j < 8; j++) hh[j] = __float2half_rn(er[j]);
        *(uint4*)&d_h16[(size_t)node * 128 + seg * 8] = *(uint4*)hh;
        return;
    } else return;
    __nv_bfloat16 h = __float2bfloat16(v);
    hi[oidx] = h;
    lo[oidx] = __float2bfloat16(v - __bfloat162float(h));
}

// ======================= precompute ==========================================
__global__ void k_histB(const int* __restrict__ snd, const int* __restrict__ rcv,
                        const int* __restrict__ gsnd, const int* __restrict__ grcv) {
    int e = blockIdx.x * blockDim.x + threadIdx.x;
    if (e < EE) {
        atomicAdd(&d_cntOutM[snd[e]], 1); atomicAdd(&d_cntInM[rcv[e]], 1);
    } else if (e < EE + EEG) {
        int g = e - EE;
        atomicAdd(&d_cntOutG[gsnd[g]], 1); atomicAdd(&d_cntInG[grcv[g]], 1);
    }
}

__global__ void k_scanA() {
    int set = blockIdx.x >> 8;
    int t = threadIdx.x;
    int i = (blockIdx.x & 255) * 256 + t;
    const int* cnt  = set ? d_cntInG  : d_cntInM;
    const int* cntO = set ? d_cntOutG : d_cntOutM;
    float* sA = set ? d_s2 : d_s1;
    float* cA = set ? d_c2 : d_c1;
    float* rA = set ? d_r2 : d_r1;
    int cv = cnt[i];
    float sv = rsqrtf((float)(cntO[i] + 1));
    sA[i] = sv;
    cA[i] = sv;
    rA[i] = rsqrtf((float)(cv + 1));
    __shared__ int red[256];
    red[t] = cv;
    __syncthreads();
    for (int d = 128; d > 0; d >>= 1) {
        if (t < d) red[t] += red[t + d];
        __syncthreads();
    }
    if (t == 0) d_psum[blockIdx.x] = red[0];
}

__global__ void k_scanM() {
    int set = blockIdx.x;
    int t = threadIdx.x;
    __shared__ int ps[256];
    int v = d_psum[set * 256 + t];
    ps[t] = v;
    __syncthreads();
    for (int d = 1; d < 256; d <<= 1) {
        int x = 0;
        if (t >= d) x = ps[t - d];
        __syncthreads();
        ps[t] += x;
        __syncthreads();
    }
    d_pbase[set * 256 + t] = ps[t] - v;
    if (t == 255) {
        int* off = set ? d_offG : d_offM;
        off[NN] = ps[255];
    }
}

__global__ void k_scanC() {
    int set = blockIdx.x >> 8;
    int b = blockIdx.x & 255;
    int t = threadIdx.x;
    int i = b * 256 + t;
    const int* cnt = set ? d_cntInG : d_cntInM;
    int* off = set ? d_offG : d_offM;
    int* cur = set ? d_curG : d_curM;
    __shared__ int ps[256];
    int v = cnt[i];
    ps[t] = v;
    __syncthreads();
    for (int d = 1; d < 256; d <<= 1) {
        int x = 0;
        if (t >= d) x = ps[t - d];
        __syncthreads();
        ps[t] += x;
        __syncthreads();
    }
    int excl = ps[t] - v + d_pbase[set * 256 + b];
    off[i] = excl;
    cur[i] = excl;
}

__global__ void k_scatB(const int* __restrict__ snd, const int* __restrict__ rcv,
                        const int* __restrict__ gsnd, const int* __restrict__ grcv) {
    int e = blockIdx.x * blockDim.x + threadIdx.x;
    if (e < EE) {
        int s = snd[e], r = rcv[e];
        int p = atomicAdd(&d_curM[r], 1);
        d_csrM[p] = s;
        atomicAdd(&d_c1[r], d_s1[s]);
    } else if (e < EE + EEG) {
        int g = e - EE;
        int s = gsnd[g], r = grcv[g];
        int p = atomicAdd(&d_curG[r], 1);
        d_csrG[p] = s;
        atomicAdd(&d_c2[r], d_s2[s]);
    }
}

// ======================= pull aggregation (fp16 gather, unroll-4) ============
__device__ __forceinline__ void fma_h16(float4& acc, uint2 v, float c) {
    float2 a = __half22float2(*(__half2*)&v.x);
    float2 b = __half22float2(*(__half2*)&v.y);
    acc.x = fmaf(a.x, c, acc.x);
    acc.y = fmaf(a.y, c, acc.y);
    acc.z = fmaf(b.x, c, acc.z);
    acc.w = fmaf(b.y, c, acc.w);
}

__global__ void k_aggB() {
    int gw   = (blockIdx.x * blockDim.x + threadIdx.x) >> 5;  // 0 .. 2*NN-1
    int lane = threadIdx.x & 31;
    int isG  = gw >= NN;
    int node = gw - (isG ? NN : 0);
    if (gw >= 2 * NN) return;
    const int* off = isG ? d_offG : d_offM;
    const int* csr = isG ? d_csrG : d_csrM;
    const float* sn = isG ? d_s2 : d_s1;
    __nv_bfloat16* oHi = isG ? d_gHi : d_mHi;
    __nv_bfloat16* oLo = isG ? d_gLo : d_mLo;
    const __half* h16 = d_h16;

    float s0 = sn[node];
    float4 acc = {0.f, 0.f, 0.f, 0.f};
    uint2 sv = *(const uint2*)(h16 + (size_t)node * 128 + lane * 4);
    fma_h16(acc, sv, s0);
    int e  = off[node];
    int e1 = off[node + 1];
    for (; e + 4 <= e1; e += 4) {
        int i0 = csr[e], i1 = csr[e + 1], i2 = csr[e + 2], i3 = csr[e + 3];
        float c0 = sn[i0], c1 = sn[i1], c2 = sn[i2], c3 = sn[i3];
        uint2 v0 = *(const uint2*)(h16 + (size_t)i0 * 128 + lane * 4);
        uint2 v1 = *(const uint2*)(h16 + (size_t)i1 * 128 + lane * 4);
        uint2 v2 = *(const uint2*)(h16 + (size_t)i2 * 128 + lane * 4);
        uint2 v3 = *(const uint2*)(h16 + (size_t)i3 * 128 + lane * 4);
        fma_h16(acc, v0, c0);
        fma_h16(acc, v1, c1);
        fma_h16(acc, v2, c2);
        fma_h16(acc, v3, c3);
    }
    for (; e < e1; e++) {
        int s = csr[e];
        uint2 v = *(const uint2*)(h16 + (size_t)s * 128 + lane * 4);
        fma_h16(acc, v, sn[s]);
    }
    __nv_bfloat16 hv[4], lv[4];
    float av[4] = {acc.x, acc.y, acc.z, acc.w};
#pragma unroll
    for (int j = 0; j < 4; j++) {
        hv[j] = __float2bfloat16(av[j]);
        lv[j] = __float2bfloat16(av[j] - __bfloat162float(hv[j]));
    }
    size_t p = (size_t)node * 128 + lane * 4;
    *(uint2*)&oHi[p] = *(uint2*)hv;
    *(uint2*)&oLo[p] = *(uint2*)lv;
}

// ======================= HMMA GEMM (cp.async double-buffered) ================
#define SLICE_BYTES 65536
#define SM_TOTAL    131072

__device__ __forceinline__ void stage_slice(
    uint32_t sbuf,
    const __nv_bfloat16* Ah, const __nv_bfloat16* Al,
    const __nv_bfloat16* wtHi, const __nv_bfloat16* wtLo,
    int rowBase, int K, int c, int ks, int tid) {
#pragma unroll
    for (int j = 0; j < 16; j++) {
        int tile = j >> 2;
        int cidx = tid + (j & 3) * 256;
        int r = cidx >> 3, ch = cidx & 7;
        uint32_t dst = sbuf + tile * 16384 + (uint32_t)r * 128 +
                       (uint32_t)((ch * 16) ^ ((r & 7) << 4));
        const __nv_bfloat16* src;
        if (tile == 0)      src = Ah   + (size_t)(rowBase + r) * 128 + ks * 64 + ch * 8;
        else if (tile == 1) src = Al   + (size_t)(rowBase + r) * 128 + ks * 64 + ch * 8;
        else if (tile == 2) src = wtHi + (size_t)r * K + c * 128 + ks * 64 + ch * 8;
        else                src = wtLo + (size_t)r * K + c * 128 + ks * 64 + ch * 8;
        cp_async16(dst, src);
    }
    asm volatile("cp.async.commit_group;" ::: "memory");
}

__device__ __forceinline__ void mma_compute_slice(
    uint32_t base, int ra_base, uint32_t kxA, uint32_t xorA,
    int rb_base, uint32_t kxB, uint32_t xorB, float acc[16][4]) {
#pragma unroll
    for (int ka = 0; ka < 4; ka++) {
        uint32_t fAh[2][4], fAl[2][4];
#pragma unroll
        for (int ma = 0; ma < 2; ma++) {
            uint32_t off = (uint32_t)(ra_base + ma * 16) * 128 +
                           (((uint32_t)(ka * 32) + kxA) ^ xorA);
            ldsm4(fAh[ma], base + off);
            ldsm4(fAl[ma], base + 16384 + off);
        }
#pragma unroll
        for (int nb = 0; nb < 4; nb++) {
            uint32_t off = (uint32_t)(rb_base + nb * 16) * 128 +
                           (((uint32_t)(ka * 32) + kxB) ^ xorB);
            uint32_t wh[4], wl[4];
            ldsm4(wh, base + 32768 + off);
            ldsm4(wl, base + 49152 + off);
#pragma unroll
            for (int ma = 0; ma < 2; ma++) {
                float* a0 = acc[ma * 8 + nb * 2];
                float* a1 = acc[ma * 8 + nb * 2 + 1];
                mma16816(a0, fAh[ma], wh);
                mma16816(a1, fAh[ma], wh + 2);
                mma16816(a0, fAl[ma], wh);
                mma16816(a1, fAl[ma], wh + 2);
                mma16816(a0, fAh[ma], wl);
                mma16816(a1, fAh[ma], wl + 2);
            }
        }
    }
}

__device__ __forceinline__ void mma_body(
    const __nv_bfloat16* aHi, const __nv_bfloat16* aLo,
    const __nv_bfloat16* gHi, const __nv_bfloat16* gLo,
    const __nv_bfloat16* wtHi, const __nv_bfloat16* wtLo,
    int K, const float* bias, const float* crow, const float* rrow,
    int relu, float* outF, __half* outH16,
    __nv_bfloat16* outHi, __nv_bfloat16* outLo,
    int rowBase, char* smem) {
    uint32_t sb = smem_to_u32(smem);
    int tid = threadIdx.x;
    int wid = tid >> 5;
    int l   = tid & 31;
    int m0 = (wid >> 1) * 32;
    int n0 = (wid & 1) * 64;

    int ra_base = m0 + (l & 7) + ((l >> 3) & 1) * 8;
    uint32_t kxA = ((l >> 4) & 1) * 16;
    uint32_t xorA = (uint32_t)((ra_base & 7) << 4);
    int rb_base = n0 + (l & 7) + ((l >> 4) & 1) * 8;
    uint32_t kxB = ((l >> 3) & 1) * 16;
    uint32_t xorB = (uint32_t)((rb_base & 7) << 4);

    float acc[16][4];
#pragma unroll
    for (int i = 0; i < 16; i++)
#pragma unroll
        for (int j = 0; j < 4; j++) acc[i][j] = 0.f;

    int nslices = K >> 6;
    stage_slice(sb, aHi, aLo, wtHi, wtLo, rowBase, K, 0, 0, tid);
    for (int s = 0; s < nslices; s++) {
        if (s + 1 < nslices) {
            int c = (s + 1) >> 1, ks = (s + 1) & 1;
            stage_slice(sb + ((s + 1) & 1) * SLICE_BYTES,
                        c ? gHi : aHi, c ? gLo : aLo, wtHi, wtLo,
                        rowBase, K, c, ks, tid);
            asm volatile("cp.async.wait_group 1;" ::: "memory");
        } else {
            asm volatile("cp.async.wait_group 0;" ::: "memory");
        }
        __syncthreads();
        mma_compute_slice(sb + (s & 1) * SLICE_BYTES,
                          ra_base, kxA, xorA, rb_base, kxB, xorB, acc);
        __syncthreads();
    }

    int gid = l >> 2, tig = l & 3;
#pragma unroll
    for (int ma = 0; ma < 2; ma++) {
        int r0 = rowBase + m0 + ma * 16 + gid;
        int r1 = r0 + 8;
        float cm0 = crow ? crow[r0] : 1.f, rm0 = rrow ? rrow[r0] : 1.f;
        float cm1 = crow ? crow[r1] : 1.f, rm1 = rrow ? rrow[r1] : 1.f;
#pragma unroll
        for (int na = 0; na < 8; na++) {
            int col = n0 + na * 8 + tig * 2;
            float b0 = bias[col], b1 = bias[col + 1];
            float* ac = acc[ma * 8 + na];
            float o00 = (ac[0] + b0 * cm0) * rm0;
            float o01 = (ac[1] + b1 * cm0) * rm0;
            float o10 = (ac[2] + b0 * cm1) * rm1;
            float o11 = (ac[3] + b1 * cm1) * rm1;
            if (relu) {
                o00 = fmaxf(o00, 0.f); o01 = fmaxf(o01, 0.f);
                o10 = fmaxf(o10, 0.f); o11 = fmaxf(o11, 0.f);
            }
            if (outH16) {
                __half2 q0 = __floats2half2_rn(o00, o01);
                __half2 q1 = __floats2half2_rn(o10, o11);
                *(__half2*)&outH16[(size_t)r0 * 128 + col] = q0;
                *(__half2*)&outH16[(size_t)r1 * 128 + col] = q1;
            }
            if (outF) {
                *(float2*)&outF[(size_t)r0 * 128 + col] = make_float2(o00, o01);
                *(float2*)&outF[(size_t)r1 * 128 + col] = make_float2(o10, o11);
            }
            if (outHi) {
                __nv_bfloat16 h00 = __float2bfloat16(o00), h01 = __float2bfloat16(o01);
                __nv_bfloat16 h10 = __float2bfloat16(o10), h11 = __float2bfloat16(o11);
                __nv_bfloat162 hp0; hp0.x = h00; hp0.y = h01;
                __nv_bfloat162 hp1; hp1.x = h10; hp1.y = h11;
                __nv_bfloat162 lp0;
                lp0.x = __float2bfloat16(o00 - __bfloat162float(h00));
                lp0.y = __float2bfloat16(o01 - __bfloat162float(h01));
                __nv_bfloat162 lp1;
                lp1.x = __float2bfloat16(o10 - __bfloat162float(h10));
                lp1.y = __float2bfloat16(o11 - __bfloat162float(h11));
                *(__nv_bfloat162*)&outHi[(size_t)r0 * 128 + col] = hp0;
                *(__nv_bfloat162*)&outHi[(size_t)r1 * 128 + col] = hp1;
                *(__nv_bfloat162*)&outLo[(size_t)r0 * 128 + col] = lp0;
                *(__nv_bfloat162*)&outLo[(size_t)r1 * 128 + col] = lp1;
            }
        }
    }
}

__global__ void __launch_bounds__(256)
k_mmaS(const __nv_bfloat16* aHi, const __nv_bfloat16* aLo,
       const __nv_bfloat16* gHi, const __nv_bfloat16* gLo,
       const __nv_bfloat16* wtHi, const __nv_bfloat16* wtLo,
       int K, const float* bias, const float* crow, const float* rrow,
       int relu, float* outF, __half* outH16,
       __nv_bfloat16* outHi, __nv_bfloat16* outLo) {
    extern __shared__ __align__(16) char smem[];
    mma_body(aHi, aLo, gHi, gLo, wtHi, wtLo, K, bias, crow, rrow,
             relu, outF, outH16, outHi, outLo, blockIdx.x * 128, smem);
}

__global__ void __launch_bounds__(256)
k_mmaD(const __nv_bfloat16* a1Hi, const __nv_bfloat16* a1Lo,
       const __nv_bfloat16* wt1Hi, const __nv_bfloat16* wt1Lo,
       const float* bias1, const float* crow1, const float* rrow1,
       __nv_bfloat16* out1Hi, __nv_bfloat16* out1Lo,
       const __nv_bfloat16* a2Hi, const __nv_bfloat16* a2Lo,
       const __nv_bfloat16* wt2Hi, const __nv_bfloat16* wt2Lo,
       const float* bias2, const float* crow2, const float* rrow2,
       __nv_bfloat16* out2Hi, __nv_bfloat16* out2Lo) {
    extern __shared__ __align__(16) char smem[];
    if (blockIdx.x < 512)
        mma_body(a1Hi, a1Lo, nullptr, nullptr, wt1Hi, wt1Lo, 128,
                 bias1, crow1, rrow1, 0, nullptr, nullptr, out1Hi, out1Lo,
                 blockIdx.x * 128, smem);
    else
        mma_body(a2Hi, a2Lo, nullptr, nullptr, wt2Hi, wt2Lo, 128,
                 bias2, crow2, rrow2, 0, nullptr, nullptr, out2Hi, out2Lo,
                 (blockIdx.x - 512) * 128, smem);
}

// ======================= edge logits =========================================
__global__ void k_edge_logits(const float* __restrict__ lg, const int* __restrict__ snd,
                              const int* __restrict__ rcv, float* __restrict__ out) {
    int gw   = (blockIdx.x * blockDim.x + threadIdx.x) >> 5;
    int lane = threadIdx.x & 31;
    if (gw >= EE) return;
    const float4* l4 = (const float4*)lg;
    int s = snd[gw], r = rcv[gw];
    float4 a = l4[(size_t)s * 32 + lane];
    float4 b = l4[(size_t)r * 32 + lane];
    float p = a.x * b.x + a.y * b.y + a.z * b.z + a.w * b.w;
#pragma unroll
    for (int o = 16; o > 0; o >>= 1) p += __shfl_down_sync(0xffffffffu, p, o);
    if (lane == 0) out[gw] = p;
}

// ======================= fused value head (one kernel) =======================
#define VAL_SMEM (128*128*4 + 2*32*128*4)   // W (64KB) + v ping-pong (32KB)

__global__ void __launch_bounds__(256)
k_value(const float* __restrict__ h, const float* __restrict__ ew,
        const float* __restrict__ eb, const float* __restrict__ wo,
        const float* __restrict__ bo, float* __restrict__ out) {
    extern __shared__ __align__(16) float vsm[];
    float* Ws  = vsm;
    float* vb0 = vsm + 16384;
    float* vb1 = vb0 + 4096;
    int tid = threadIdx.x;
    int g0 = blockIdx.x * 32;

    for (int idx = tid; idx < 32 * 128; idx += 256) {
        int g = idx >> 7, col = idx & 127;
        const float* hp = h + ((size_t)(g0 + g) * 64 + 1) * 128 + col;
        float acc = 0.f;
        for (int j = 0; j < 63; j++) acc += hp[j * 128];
        vb0[idx] = acc * (1.f / 63.f);
    }

    float* cur = vb0;
    float* nxt = vb1;
    for (int layer = 0; layer < 5; layer++) {
        __syncthreads();
        for (int idx = tid; idx < 128 * 32; idx += 256)
            ((float4*)Ws)[idx] = ((const float4*)(ew + (size_t)layer * 16384))[idx];
        __syncthreads();
        for (int idx = tid; idx < 32 * 32; idx += 256) {
            int g = idx >> 5, cg = (idx & 31) * 4;
            const float* vr = &cur[g * 128];
            float4 acc = *(const float4*)&eb[layer * 128 + cg];
            for (int k = 0; k < 128; k++) {
                float av = vr[k];
                float4 w = *(const float4*)&Ws[k * 128 + cg];
                acc.x = fmaf(av, w.x, acc.x);
                acc.y = fmaf(av, w.y, acc.y);
                acc.z = fmaf(av, w.z, acc.z);
                acc.w = fmaf(av, w.w, acc.w);
            }
            acc.x = fmaxf(acc.x, 0.f); acc.y = fmaxf(acc.y, 0.f);
            acc.z = fmaxf(acc.z, 0.f); acc.w = fmaxf(acc.w, 0.f);
            *(float4*)&nxt[g * 128 + cg] = acc;
        }
        float* t = cur; cur = nxt; nxt = t;
    }
    __syncthreads();

    int w = tid >> 5, l = tid & 31;
    for (int sub = 0; sub < 4; sub++) {
        int g = w * 4 + sub;
        const float* vr = &cur[g * 128];
        float p = vr[l] * wo[l] + vr[l + 32] * wo[l + 32] +
                  vr[l + 64] * wo[l + 64] + vr[l + 96] * wo[l + 96];
#pragma unroll
        for (int o = 16; o > 0; o >>= 1) p += __shfl_down_sync(0xffffffffu, p, o);
        if (l == 0) out[EE + g0 + g] = tanhf(p + bo[0]);
    }
}

// ======================= host launcher =======================================
extern "C" void kernel_launch(void* const* d_in, const int* in_sizes, int n_in,
                              void* d_out, int out_size) {
    const int*   nodes = (const int*)d_in[0];
    const int*   snd   = (const int*)d_in[1];
    const int*   rcv   = (const int*)d_in[2];
    const int*   gsnd  = (const int*)d_in[3];
    const int*   grcv  = (const int*)d_in[4];
    const float* embed = (const float*)d_in[6];
    const float* w1    = (const float*)d_in[7];
    const float* b1    = (const float*)d_in[8];
    const float* w2    = (const float*)d_in[9];
    const float* b2    = (const float*)d_in[10];
    const float* w3    = (const float*)d_in[11];
    const float* b3    = (const float*)d_in[12];
    const float* wl    = (const float*)d_in[13];
    const float* bl    = (const float*)d_in[14];
    const float* ew    = (const float*)d_in[15];
    const float* eb    = (const float*)d_in[16];
    const float* wo    = (const float*)d_in[17];
    const float* bo    = (const float*)d_in[18];
    float* out = (float*)d_out;

    float *h, *lg, *s1, *r1, *c1, *s2, *r2, *c2;
    __half* h16;
    __nv_bfloat16 *mHi, *mLo, *gHi, *gLo;
    __nv_bfloat16 *wt1h, *wt1l, *wt2h, *wt2l, *wt3h, *wt3l, *wtlh, *wtll;
    cudaGetSymbolAddress((void**)&h,    d_h);
    cudaGetSymbolAddress((void**)&h16,  d_h16);
    cudaGetSymbolAddress((void**)&lg,   d_lg);
    cudaGetSymbolAddress((void**)&mHi,  d_mHi);
    cudaGetSymbolAddress((void**)&mLo,  d_mLo);
    cudaGetSymbolAddress((void**)&gHi,  d_gHi);
    cudaGetSymbolAddress((void**)&gLo,  d_gLo);
    cudaGetSymbolAddress((void**)&wt1h, d_wt1h);
    cudaGetSymbolAddress((void**)&wt1l, d_wt1l);
    cudaGetSymbolAddress((void**)&wt2h, d_wt2h);
    cudaGetSymbolAddress((void**)&wt2l, d_wt2l);
    cudaGetSymbolAddress((void**)&wt3h, d_wt3h);
    cudaGetSymbolAddress((void**)&wt3l, d_wt3l);
    cudaGetSymbolAddress((void**)&wtlh, d_wtlh);
    cudaGetSymbolAddress((void**)&wtll, d_wtll);
    cudaGetSymbolAddress((void**)&s1,   d_s1);
    cudaGetSymbolAddress((void**)&r1,   d_r1);
    cudaGetSymbolAddress((void**)&c1,   d_c1);
    cudaGetSymbolAddress((void**)&s2,   d_s2);
    cudaGetSymbolAddress((void**)&r2,   d_r2);
    cudaGetSymbolAddress((void**)&c2,   d_c2);

    cudaFuncSetAttribute(k_mmaS, cudaFuncAttributeMaxDynamicSharedMemorySize, SM_TOTAL);
    cudaFuncSetAttribute(k_mmaD, cudaFuncAttributeMaxDynamicSharedMemorySize, SM_TOTAL);
    cudaFuncSetAttribute(k_value, cudaFuncAttributeMaxDynamicSharedMemorySize, VAL_SMEM);

    // ---- weight conversion + counter zero + embed (one launch) ----
    k_wt_all<<<(ALL_TOTAL + 255) / 256, 256>>>(w1, w2, w3, wl, nodes, embed);

    // ---- degree / CSR precompute (layer-invariant, parallel scan) ----
    k_histB<<<(EE + EEG + 255) / 256, 256>>>(snd, rcv, gsnd, grcv);
    k_scanA<<<512, 256>>>();
    k_scanM<<<2, 256>>>();
    k_scanC<<<512, 256>>>();
    k_scatB<<<(EE + EEG + 255) / 256, 256>>>(snd, rcv, gsnd, grcv);

    // ---- 7 GNN layers ----
    for (int i = 0; i < 7; i++) {
        k_aggB<<<2 * NN * 32 / 256, 256>>>();
        k_mmaD<<<1024, 256, SM_TOTAL>>>(
            mHi, mLo, wt1h + (size_t)i * 16384, wt1l + (size_t)i * 16384,
            b1 + i * 128, c1, r1, mHi, mLo,
            gHi, gLo, wt2h + (size_t)i * 16384, wt2l + (size_t)i * 16384,
            b2 + i * 128, c2, r2, gHi, gLo);
        int last = (i == 6);
        k_mmaS<<<512, 256, SM_TOTAL>>>(mHi, mLo, gHi, gLo,
                                       wt3h + (size_t)i * 32768, wt3l + (size_t)i * 32768,
                                       256, b3 + i * 128, nullptr, nullptr, 1,
                                       last ? h : nullptr, h16,
                                       last ? mHi : nullptr, last ? mLo : nullptr);
    }

    // ---- policy head ----
    k_mmaS<<<512, 256, SM_TOTAL>>>(mHi, mLo, nullptr, nullptr, wtlh, wtll,
                                   128, bl, nullptr, nullptr, 0,
                                   lg, nullptr, nullptr, nullptr);
    k_edge_logits<<<(EE * 32) / 256, 256>>>(lg, snd, rcv, out);

    // ---- value head (fused) ----
    k_value<<<32, 256, VAL_SMEM>>>(h, ew, eb, wo, bo, out);
}

// round 13
// speedup vs baseline: 1.2879x; 1.0239x over previous
#include <cuda_runtime.h>
#include <cuda_bf16.h>
#include <cuda_fp16.h>
#include <math.h>
#include <stdint.h>

#define NN   65536
#define BB   1024
#define EE   2097152
#define EEG  524288
#define DIM  128

// ======================= portable PTX helpers ================================
__device__ __forceinline__ uint32_t smem_to_u32(const void* p) {
    uint32_t a;
    asm("{ .reg .u64 t; cvta.to.shared.u64 t, %1; cvt.u32.u64 %0, t; }" : "=r"(a) : "l"(p));
    return a;
}

__device__ __forceinline__ void ldsm4(uint32_t* r, uint32_t addr) {
    asm volatile("ldmatrix.sync.aligned.m8n8.x4.shared.b16 {%0,%1,%2,%3}, [%4];"
                 : "=r"(r[0]), "=r"(r[1]), "=r"(r[2]), "=r"(r[3]) : "r"(addr));
}

__device__ __forceinline__ void mma16816(float* c, const uint32_t* a, const uint32_t* b) {
    asm volatile("mma.sync.aligned.m16n8k16.row.col.f32.bf16.bf16.f32 "
                 "{%0,%1,%2,%3}, {%4,%5,%6,%7}, {%8,%9}, {%0,%1,%2,%3};"
                 : "+f"(c[0]), "+f"(c[1]), "+f"(c[2]), "+f"(c[3])
                 : "r"(a[0]), "r"(a[1]), "r"(a[2]), "r"(a[3]), "r"(b[0]), "r"(b[1]));
}

__device__ __forceinline__ void cp_async16(uint32_t dst, const void* src) {
    asm volatile("cp.async.cg.shared.global [%0], [%1], 16;" :: "r"(dst), "l"(src) : "memory");
}

// ======================= static scratch ======================================
__device__ float  d_h  [(size_t)NN * DIM];   // node features fp32 (last layer; value head)
__device__ __half d_h16[(size_t)NN * DIM];   // node features fp16 (aggregation gather source)
__device__ float  d_lg [(size_t)NN * DIM];   // logit-head features (fp32 — REQUIRED, see R10)

__device__ __nv_bfloat16 d_mHi[(size_t)NN * DIM], d_mLo[(size_t)NN * DIM];
__device__ __nv_bfloat16 d_gHi[(size_t)NN * DIM], d_gLo[(size_t)NN * DIM];

// converted transposed weights (bf16 hi/lo), layout [n][K]
__device__ __nv_bfloat16 d_wt1h[7*128*128], d_wt1l[7*128*128];
__device__ __nv_bfloat16 d_wt2h[7*128*128], d_wt2l[7*128*128];
__device__ __nv_bfloat16 d_wt3h[7*128*256], d_wt3l[7*128*256];
__device__ __nv_bfloat16 d_wtlh[128*128],   d_wtll[128*128];

__device__ int d_csrM[EE];
__device__ int d_csrG[EEG];
__device__ int d_offM[NN + 1];
__device__ int d_offG[NN + 1];
__device__ int d_curM[NN];
__device__ int d_curG[NN];
__device__ int d_cntOutM[NN], d_cntInM[NN], d_cntOutG[NN], d_cntInG[NN];
__device__ float d_s1[NN], d_r1[NN], d_c1[NN];
__device__ float d_s2[NN], d_r2[NN], d_c2[NN];
__device__ int d_psum[512];
__device__ int d_pbase[512];

// ======== weight convert + counter zero + embed->fp16 (one launch) ==========
#define WT_S1 (7*16384)
#define WT_S3 (7*32768)
#define WT_TOTAL (2*WT_S1 + WT_S3 + 16384)
#define ALL_TOTAL (WT_TOTAL + NN*16)
__global__ void k_wt_all(const float* __restrict__ w1, const float* __restrict__ w2,
                         const float* __restrict__ w3, const float* __restrict__ wl,
                         const int* __restrict__ nodes, const float* __restrict__ embed) {
    int id = blockIdx.x * blockDim.x + threadIdx.x;
    if (id < NN) { d_cntOutM[id] = 0; d_cntInM[id] = 0; d_cntOutG[id] = 0; d_cntInG[id] = 0; }
    float v;
    __nv_bfloat16 *hi, *lo;
    int oidx;
    if (id < WT_S1) {
        int layer = id >> 14, w = id & 16383;
        int n = w >> 7, k = w & 127;
        v = w1[(size_t)(layer << 14) + k * 128 + n];
        hi = d_wt1h; lo = d_wt1l; oidx = (layer << 14) + n * 128 + k;
    } else if (id < 2 * WT_S1) {
        int id2 = id - WT_S1;
        int layer = id2 >> 14, w = id2 & 16383;
        int n = w >> 7, k = w & 127;
        v = w2[(size_t)(layer << 14) + k * 128 + n];
        hi = d_wt2h; lo = d_wt2l; oidx = (layer << 14) + n * 128 + k;
    } else if (id < 2 * WT_S1 + WT_S3) {
        int id3 = id - 2 * WT_S1;
        int layer = id3 >> 15, w = id3 & 32767;
        int n = w >> 8, k = w & 255;
        v = w3[(size_t)(layer << 15) + k * 128 + n];
        hi = d_wt3h; lo = d_wt3l; oidx = (layer << 15) + n * 256 + k;
    } else if (id < WT_TOTAL) {
        int id4 = id - (2 * WT_S1 + WT_S3);
        int n = id4 >> 7, k = id4 & 127;
        v = wl[k * 128 + n];
        hi = d_wtlh; lo = d_wtll; oidx = n * 128 + k;
    } else if (id < ALL_TOTAL) {
        int e = id - WT_TOTAL;
        int node = e >> 4, seg = e & 15;
        const float* er = embed + (size_t)nodes[node] * 128 + seg * 8;
        __half hh[8];
#pragma unroll
        for (int j = 0; j < 8; j++) hh[j] = __float2half_rn(er[j]);
        *(uint4*)&d_h16[(size_t)node * 128 + seg * 8] = *(uint4*)hh;
        return;
    } else return;
    __nv_bfloat16 h = __float2bfloat16(v);
    hi[oidx] = h;
    lo[oidx] = __float2bfloat16(v - __bfloat162float(h));
}

// ======================= precompute ==========================================
__global__ void k_histB(const int* __restrict__ snd, const int* __restrict__ rcv,
                        const int* __restrict__ gsnd, const int* __restrict__ grcv) {
    int e = blockIdx.x * blockDim.x + threadIdx.x;
    if (e < EE) {
        atomicAdd(&d_cntOutM[snd[e]], 1); atomicAdd(&d_cntInM[rcv[e]], 1);
    } else if (e < EE + EEG) {
        int g = e - EE;
        atomicAdd(&d_cntOutG[gsnd[g]], 1); atomicAdd(&d_cntInG[grcv[g]], 1);
    }
}

__global__ void k_scanA() {
    int set = blockIdx.x >> 8;
    int t = threadIdx.x;
    int i = (blockIdx.x & 255) * 256 + t;
    const int* cnt  = set ? d_cntInG  : d_cntInM;
    const int* cntO = set ? d_cntOutG : d_cntOutM;
    float* sA = set ? d_s2 : d_s1;
    float* cA = set ? d_c2 : d_c1;
    float* rA = set ? d_r2 : d_r1;
    int cv = cnt[i];
    float sv = rsqrtf((float)(cntO[i] + 1));
    sA[i] = sv;
    cA[i] = sv;
    rA[i] = rsqrtf((float)(cv + 1));
    __shared__ int red[256];
    red[t] = cv;
    __syncthreads();
    for (int d = 128; d > 0; d >>= 1) {
        if (t < d) red[t] += red[t + d];
        __syncthreads();
    }
    if (t == 0) d_psum[blockIdx.x] = red[0];
}

__global__ void k_scanM() {
    int set = blockIdx.x;
    int t = threadIdx.x;
    __shared__ int ps[256];
    int v = d_psum[set * 256 + t];
    ps[t] = v;
    __syncthreads();
    for (int d = 1; d < 256; d <<= 1) {
        int x = 0;
        if (t >= d) x = ps[t - d];
        __syncthreads();
        ps[t] += x;
        __syncthreads();
    }
    d_pbase[set * 256 + t] = ps[t] - v;
    if (t == 255) {
        int* off = set ? d_offG : d_offM;
        off[NN] = ps[255];
    }
}

__global__ void k_scanC() {
    int set = blockIdx.x >> 8;
    int b = blockIdx.x & 255;
    int t = threadIdx.x;
    int i = b * 256 + t;
    const int* cnt = set ? d_cntInG : d_cntInM;
    int* off = set ? d_offG : d_offM;
    int* cur = set ? d_curG : d_curM;
    __shared__ int ps[256];
    int v = cnt[i];
    ps[t] = v;
    __syncthreads();
    for (int d = 1; d < 256; d <<= 1) {
        int x = 0;
        if (t >= d) x = ps[t - d];
        __syncthreads();
        ps[t] += x;
        __syncthreads();
    }
    int excl = ps[t] - v + d_pbase[set * 256 + b];
    off[i] = excl;
    cur[i] = excl;
}

__global__ void k_scatB(const int* __restrict__ snd, const int* __restrict__ rcv,
                        const int* __restrict__ gsnd, const int* __restrict__ grcv) {
    int e = blockIdx.x * blockDim.x + threadIdx.x;
    if (e < EE) {
        int s = snd[e], r = rcv[e];
        int p = atomicAdd(&d_curM[r], 1);
        d_csrM[p] = s;
        atomicAdd(&d_c1[r], d_s1[s]);
    } else if (e < EE + EEG) {
        int g = e - EE;
        int s = gsnd[g], r = grcv[g];
        int p = atomicAdd(&d_curG[r], 1);
        d_csrG[p] = s;
        atomicAdd(&d_c2[r], d_s2[s]);
    }
}

// ======================= pull aggregation (fp16 gather, unroll-8) ============
__device__ __forceinline__ void fma_h16(float4& acc, uint2 v, float c) {
    float2 a = __half22float2(*(__half2*)&v.x);
    float2 b = __half22float2(*(__half2*)&v.y);
    acc.x = fmaf(a.x, c, acc.x);
    acc.y = fmaf(a.y, c, acc.y);
    acc.z = fmaf(b.x, c, acc.z);
    acc.w = fmaf(b.y, c, acc.w);
}

__global__ void k_aggB() {
    int gw   = (blockIdx.x * blockDim.x + threadIdx.x) >> 5;  // 0 .. 2*NN-1
    int lane = threadIdx.x & 31;
    int isG  = gw >= NN;
    int node = gw - (isG ? NN : 0);
    if (gw >= 2 * NN) return;
    const int* off = isG ? d_offG : d_offM;
    const int* csr = isG ? d_csrG : d_csrM;
    const float* sn = isG ? d_s2 : d_s1;
    __nv_bfloat16* oHi = isG ? d_gHi : d_mHi;
    __nv_bfloat16* oLo = isG ? d_gLo : d_mLo;
    const __half* h16 = d_h16;

    float s0 = sn[node];
    float4 acc = {0.f, 0.f, 0.f, 0.f};
    uint2 sv = *(const uint2*)(h16 + (size_t)node * 128 + lane * 4);
    fma_h16(acc, sv, s0);
    int e  = off[node];
    int e1 = off[node + 1];
    // unroll-8: batch indices + scales, then 8 independent 256B gathers
    for (; e + 8 <= e1; e += 8) {
        int ix[8];
        float cs[8];
#pragma unroll
        for (int j = 0; j < 8; j++) ix[j] = csr[e + j];
#pragma unroll
        for (int j = 0; j < 8; j++) cs[j] = sn[ix[j]];
        uint2 vv[8];
#pragma unroll
        for (int j = 0; j < 8; j++)
            vv[j] = *(const uint2*)(h16 + (size_t)ix[j] * 128 + lane * 4);
#pragma unroll
        for (int j = 0; j < 8; j++) fma_h16(acc, vv[j], cs[j]);
    }
    for (; e + 4 <= e1; e += 4) {
        int i0 = csr[e], i1 = csr[e + 1], i2 = csr[e + 2], i3 = csr[e + 3];
        float c0 = sn[i0], c1 = sn[i1], c2 = sn[i2], c3 = sn[i3];
        uint2 v0 = *(const uint2*)(h16 + (size_t)i0 * 128 + lane * 4);
        uint2 v1 = *(const uint2*)(h16 + (size_t)i1 * 128 + lane * 4);
        uint2 v2 = *(const uint2*)(h16 + (size_t)i2 * 128 + lane * 4);
        uint2 v3 = *(const uint2*)(h16 + (size_t)i3 * 128 + lane * 4);
        fma_h16(acc, v0, c0);
        fma_h16(acc, v1, c1);
        fma_h16(acc, v2, c2);
        fma_h16(acc, v3, c3);
    }
    for (; e < e1; e++) {
        int s = csr[e];
        uint2 v = *(const uint2*)(h16 + (size_t)s * 128 + lane * 4);
        fma_h16(acc, v, sn[s]);
    }
    __nv_bfloat16 hv[4], lv[4];
    float av[4] = {acc.x, acc.y, acc.z, acc.w};
#pragma unroll
    for (int j = 0; j < 4; j++) {
        hv[j] = __float2bfloat16(av[j]);
        lv[j] = __float2bfloat16(av[j] - __bfloat162float(hv[j]));
    }
    size_t p = (size_t)node * 128 + lane * 4;
    *(uint2*)&oHi[p] = *(uint2*)hv;
    *(uint2*)&oLo[p] = *(uint2*)lv;
}

// ======================= HMMA GEMM (cp.async double-buffered, 3-pass) ========
#define SLICE_BYTES 65536
#define SM_TOTAL    131072

__device__ __forceinline__ void stage_slice(
    uint32_t sbuf,
    const __nv_bfloat16* Ah, const __nv_bfloat16* Al,
    const __nv_bfloat16* wtHi, const __nv_bfloat16* wtLo,
    int rowBase, int K, int c, int ks, int tid) {
#pragma unroll
    for (int j = 0; j < 16; j++) {
        int tile = j >> 2;
        int cidx = tid + (j & 3) * 256;
        int r = cidx >> 3, ch = cidx & 7;
        uint32_t dst = sbuf + tile * 16384 + (uint32_t)r * 128 +
                       (uint32_t)((ch * 16) ^ ((r & 7) << 4));
        const __nv_bfloat16* src;
        if (tile == 0)      src = Ah   + (size_t)(rowBase + r) * 128 + ks * 64 + ch * 8;
        else if (tile == 1) src = Al   + (size_t)(rowBase + r) * 128 + ks * 64 + ch * 8;
        else if (tile == 2) src = wtHi + (size_t)r * K + c * 128 + ks * 64 + ch * 8;
        else                src = wtLo + (size_t)r * K + c * 128 + ks * 64 + ch * 8;
        cp_async16(dst, src);
    }
    asm volatile("cp.async.commit_group;" ::: "memory");
}

__device__ __forceinline__ void mma_compute_slice(
    uint32_t base, int ra_base, uint32_t kxA, uint32_t xorA,
    int rb_base, uint32_t kxB, uint32_t xorB, float acc[16][4]) {
#pragma unroll
    for (int ka = 0; ka < 4; ka++) {
        uint32_t fAh[2][4], fAl[2][4];
#pragma unroll
        for (int ma = 0; ma < 2; ma++) {
            uint32_t off = (uint32_t)(ra_base + ma * 16) * 128 +
                           (((uint32_t)(ka * 32) + kxA) ^ xorA);
            ldsm4(fAh[ma], base + off);
            ldsm4(fAl[ma], base + 16384 + off);
        }
#pragma unroll
        for (int nb = 0; nb < 4; nb++) {
            uint32_t off = (uint32_t)(rb_base + nb * 16) * 128 +
                           (((uint32_t)(ka * 32) + kxB) ^ xorB);
            uint32_t wh[4], wl[4];
            ldsm4(wh, base + 32768 + off);
            ldsm4(wl, base + 49152 + off);
#pragma unroll
            for (int ma = 0; ma < 2; ma++) {
                float* a0 = acc[ma * 8 + nb * 2];
                float* a1 = acc[ma * 8 + nb * 2 + 1];
                mma16816(a0, fAh[ma], wh);
                mma16816(a1, fAh[ma], wh + 2);
                mma16816(a0, fAl[ma], wh);
                mma16816(a1, fAl[ma], wh + 2);
                mma16816(a0, fAh[ma], wl);
                mma16816(a1, fAh[ma], wl + 2);
            }
        }
    }
}

__device__ __forceinline__ void mma_body(
    const __nv_bfloat16* aHi, const __nv_bfloat16* aLo,
    const __nv_bfloat16* gHi, const __nv_bfloat16* gLo,
    const __nv_bfloat16* wtHi, const __nv_bfloat16* wtLo,
    int K, const float* bias, const float* crow, const float* rrow,
    int relu, float* outF, __half* outH16,
    __nv_bfloat16* outHi, __nv_bfloat16* outLo,
    int rowBase, char* smem) {
    uint32_t sb = smem_to_u32(smem);
    int tid = threadIdx.x;
    int wid = tid >> 5;
    int l   = tid & 31;
    int m0 = (wid >> 1) * 32;
    int n0 = (wid & 1) * 64;

    int ra_base = m0 + (l & 7) + ((l >> 3) & 1) * 8;
    uint32_t kxA = ((l >> 4) & 1) * 16;
    uint32_t xorA = (uint32_t)((ra_base & 7) << 4);
    int rb_base = n0 + (l & 7) + ((l >> 4) & 1) * 8;
    uint32_t kxB = ((l >> 3) & 1) * 16;
    uint32_t xorB = (uint32_t)((rb_base & 7) << 4);

    float acc[16][4];
#pragma unroll
    for (int i = 0; i < 16; i++)
#pragma unroll
        for (int j = 0; j < 4; j++) acc[i][j] = 0.f;

    int nslices = K >> 6;
    stage_slice(sb, aHi, aLo, wtHi, wtLo, rowBase, K, 0, 0, tid);
    for (int s = 0; s < nslices; s++) {
        if (s + 1 < nslices) {
            int c = (s + 1) >> 1, ks = (s + 1) & 1;
            stage_slice(sb + ((s + 1) & 1) * SLICE_BYTES,
                        c ? gHi : aHi, c ? gLo : aLo, wtHi, wtLo,
                        rowBase, K, c, ks, tid);
            asm volatile("cp.async.wait_group 1;" ::: "memory");
        } else {
            asm volatile("cp.async.wait_group 0;" ::: "memory");
        }
        __syncthreads();
        mma_compute_slice(sb + (s & 1) * SLICE_BYTES,
                          ra_base, kxA, xorA, rb_base, kxB, xorB, acc);
        __syncthreads();
    }

    int gid = l >> 2, tig = l & 3;
#pragma unroll
    for (int ma = 0; ma < 2; ma++) {
        int r0 = rowBase + m0 + ma * 16 + gid;
        int r1 = r0 + 8;
        float cm0 = crow ? crow[r0] : 1.f, rm0 = rrow ? rrow[r0] : 1.f;
        float cm1 = crow ? crow[r1] : 1.f, rm1 = rrow ? rrow[r1] : 1.f;
#pragma unroll
        for (int na = 0; na < 8; na++) {
            int col = n0 + na * 8 + tig * 2;
            float b0 = bias[col], b1 = bias[col + 1];
            float* ac = acc[ma * 8 + na];
            float o00 = (ac[0] + b0 * cm0) * rm0;
            float o01 = (ac[1] + b1 * cm0) * rm0;
            float o10 = (ac[2] + b0 * cm1) * rm1;
            float o11 = (ac[3] + b1 * cm1) * rm1;
            if (relu) {
                o00 = fmaxf(o00, 0.f); o01 = fmaxf(o01, 0.f);
                o10 = fmaxf(o10, 0.f); o11 = fmaxf(o11, 0.f);
            }
            if (outH16) {
                __half2 q0 = __floats2half2_rn(o00, o01);
                __half2 q1 = __floats2half2_rn(o10, o11);
                *(__half2*)&outH16[(size_t)r0 * 128 + col] = q0;
                *(__half2*)&outH16[(size_t)r1 * 128 + col] = q1;
            }
            if (outF) {
                *(float2*)&outF[(size_t)r0 * 128 + col] = make_float2(o00, o01);
                *(float2*)&outF[(size_t)r1 * 128 + col] = make_float2(o10, o11);
            }
            if (outHi) {
                __nv_bfloat16 h00 = __float2bfloat16(o00), h01 = __float2bfloat16(o01);
                __nv_bfloat16 h10 = __float2bfloat16(o10), h11 = __float2bfloat16(o11);
                __nv_bfloat162 hp0; hp0.x = h00; hp0.y = h01;
                __nv_bfloat162 hp1; hp1.x = h10; hp1.y = h11;
                __nv_bfloat162 lp0;
                lp0.x = __float2bfloat16(o00 - __bfloat162float(h00));
                lp0.y = __float2bfloat16(o01 - __bfloat162float(h01));
                __nv_bfloat162 lp1;
                lp1.x = __float2bfloat16(o10 - __bfloat162float(h10));
                lp1.y = __float2bfloat16(o11 - __bfloat162float(h11));
                *(__nv_bfloat162*)&outHi[(size_t)r0 * 128 + col] = hp0;
                *(__nv_bfloat162*)&outHi[(size_t)r1 * 128 + col] = hp1;
                *(__nv_bfloat162*)&outLo[(size_t)r0 * 128 + col] = lp0;
                *(__nv_bfloat162*)&outLo[(size_t)r1 * 128 + col] = lp1;
            }
        }
    }
}

__global__ void __launch_bounds__(256)
k_mmaS(const __nv_bfloat16* aHi, const __nv_bfloat16* aLo,
       const __nv_bfloat16* gHi, const __nv_bfloat16* gLo,
       const __nv_bfloat16* wtHi, const __nv_bfloat16* wtLo,
       int K, const float* bias, const float* crow, const float* rrow,
       int relu, float* outF, __half* outH16,
       __nv_bfloat16* outHi, __nv_bfloat16* outLo) {
    extern __shared__ __align__(16) char smem[];
    mma_body(aHi, aLo, gHi, gLo, wtHi, wtLo, K, bias, crow, rrow,
             relu, outF, outH16, outHi, outLo, blockIdx.x * 128, smem);
}

__global__ void __launch_bounds__(256)
k_mmaD(const __nv_bfloat16* a1Hi, const __nv_bfloat16* a1Lo,
       const __nv_bfloat16* wt1Hi, const __nv_bfloat16* wt1Lo,
       const float* bias1, const float* crow1, const float* rrow1,
       __nv_bfloat16* out1Hi, __nv_bfloat16* out1Lo,
       const __nv_bfloat16* a2Hi, const __nv_bfloat16* a2Lo,
       const __nv_bfloat16* wt2Hi, const __nv_bfloat16* wt2Lo,
       const float* bias2, const float* crow2, const float* rrow2,
       __nv_bfloat16* out2Hi, __nv_bfloat16* out2Lo) {
    extern __shared__ __align__(16) char smem[];
    if (blockIdx.x < 512)
        mma_body(a1Hi, a1Lo, nullptr, nullptr, wt1Hi, wt1Lo, 128,
                 bias1, crow1, rrow1, 0, nullptr, nullptr, out1Hi, out1Lo,
                 blockIdx.x * 128, smem);
    else
        mma_body(a2Hi, a2Lo, nullptr, nullptr, wt2Hi, wt2Lo, 128,
                 bias2, crow2, rrow2, 0, nullptr, nullptr, out2Hi, out2Lo,
                 (blockIdx.x - 512) * 128, smem);
}

// ======================= edge logits (fp32 lg — required) ====================
__global__ void k_edge_logits(const float* __restrict__ lg, const int* __restrict__ snd,
                              const int* __restrict__ rcv, float* __restrict__ out) {
    int gw   = (blockIdx.x * blockDim.x + threadIdx.x) >> 5;
    int lane = threadIdx.x & 31;
    if (gw >= EE) return;
    const float4* l4 = (const float4*)lg;
    int s = snd[gw], r = rcv[gw];
    float4 a = l4[(size_t)s * 32 + lane];
    float4 b = l4[(size_t)r * 32 + lane];
    float p = a.x * b.x + a.y * b.y + a.z * b.z + a.w * b.w;
#pragma unroll
    for (int o = 16; o > 0; o >>= 1) p += __shfl_down_sync(0xffffffffu, p, o);
    if (lane == 0) out[gw] = p;
}

// ======================= fused value head (one kernel) =======================
#define VAL_SMEM (128*128*4 + 2*32*128*4)   // W (64KB) + v ping-pong (32KB)

__global__ void __launch_bounds__(256)
k_value(const float* __restrict__ h, const float* __restrict__ ew,
        const float* __restrict__ eb, const float* __restrict__ wo,
        const float* __restrict__ bo, float* __restrict__ out) {
    extern __shared__ __align__(16) float vsm[];
    float* Ws  = vsm;
    float* vb0 = vsm + 16384;
    float* vb1 = vb0 + 4096;
    int tid = threadIdx.x;
    int g0 = blockIdx.x * 32;

    for (int idx = tid; idx < 32 * 128; idx += 256) {
        int g = idx >> 7, col = idx & 127;
        const float* hp = h + ((size_t)(g0 + g) * 64 + 1) * 128 + col;
        float acc = 0.f;
        for (int j = 0; j < 63; j++) acc += hp[j * 128];
        vb0[idx] = acc * (1.f / 63.f);
    }

    float* cur = vb0;
    float* nxt = vb1;
    for (int layer = 0; layer < 5; layer++) {
        __syncthreads();
        for (int idx = tid; idx < 128 * 32; idx += 256)
            ((float4*)Ws)[idx] = ((const float4*)(ew + (size_t)layer * 16384))[idx];
        __syncthreads();
        for (int idx = tid; idx < 32 * 32; idx += 256) {
            int g = idx >> 5, cg = (idx & 31) * 4;
            const float* vr = &cur[g * 128];
            float4 acc = *(const float4*)&eb[layer * 128 + cg];
            for (int k = 0; k < 128; k++) {
                float av = vr[k];
                float4 w = *(const float4*)&Ws[k * 128 + cg];
                acc.x = fmaf(av, w.x, acc.x);
                acc.y = fmaf(av, w.y, acc.y);
                acc.z = fmaf(av, w.z, acc.z);
                acc.w = fmaf(av, w.w, acc.w);
            }
            acc.x = fmaxf(acc.x, 0.f); acc.y = fmaxf(acc.y, 0.f);
            acc.z = fmaxf(acc.z, 0.f); acc.w = fmaxf(acc.w, 0.f);
            *(float4*)&nxt[g * 128 + cg] = acc;
        }
        float* t = cur; cur = nxt; nxt = t;
    }
    __syncthreads();

    int w = tid >> 5, l = tid & 31;
    for (int sub = 0; sub < 4; sub++) {
        int g = w * 4 + sub;
        const float* vr = &cur[g * 128];
        float p = vr[l] * wo[l] + vr[l + 32] * wo[l + 32] +
                  vr[l + 64] * wo[l + 64] + vr[l + 96] * wo[l + 96];
#pragma unroll
        for (int o = 16; o > 0; o >>= 1) p += __shfl_down_sync(0xffffffffu, p, o);
        if (l == 0) out[EE + g0 + g] = tanhf(p + bo[0]);
    }
}

// ======================= host launcher =======================================
extern "C" void kernel_launch(void* const* d_in, const int* in_sizes, int n_in,
                              void* d_out, int out_size) {
    const int*   nodes = (const int*)d_in[0];
    const int*   snd   = (const int*)d_in[1];
    const int*   rcv   = (const int*)d_in[2];
    const int*   gsnd  = (const int*)d_in[3];
    const int*   grcv  = (const int*)d_in[4];
    const float* embed = (const float*)d_in[6];
    const float* w1    = (const float*)d_in[7];
    const float* b1    = (const float*)d_in[8];
    const float* w2    = (const float*)d_in[9];
    const float* b2    = (const float*)d_in[10];
    const float* w3    = (const float*)d_in[11];
    const float* b3    = (const float*)d_in[12];
    const float* wl    = (const float*)d_in[13];
    const float* bl    = (const float*)d_in[14];
    const float* ew    = (const float*)d_in[15];
    const float* eb    = (const float*)d_in[16];
    const float* wo    = (const float*)d_in[17];
    const float* bo    = (const float*)d_in[18];
    float* out = (float*)d_out;

    float *h, *lg, *s1, *r1, *c1, *s2, *r2, *c2;
    __half* h16;
    __nv_bfloat16 *mHi, *mLo, *gHi, *gLo;
    __nv_bfloat16 *wt1h, *wt1l, *wt2h, *wt2l, *wt3h, *wt3l, *wtlh, *wtll;
    cudaGetSymbolAddress((void**)&h,    d_h);
    cudaGetSymbolAddress((void**)&h16,  d_h16);
    cudaGetSymbolAddress((void**)&lg,   d_lg);
    cudaGetSymbolAddress((void**)&mHi,  d_mHi);
    cudaGetSymbolAddress((void**)&mLo,  d_mLo);
    cudaGetSymbolAddress((void**)&gHi,  d_gHi);
    cudaGetSymbolAddress((void**)&gLo,  d_gLo);
    cudaGetSymbolAddress((void**)&wt1h, d_wt1h);
    cudaGetSymbolAddress((void**)&wt1l, d_wt1l);
    cudaGetSymbolAddress((void**)&wt2h, d_wt2h);
    cudaGetSymbolAddress((void**)&wt2l, d_wt2l);
    cudaGetSymbolAddress((void**)&wt3h, d_wt3h);
    cudaGetSymbolAddress((void**)&wt3l, d_wt3l);
    cudaGetSymbolAddress((void**)&wtlh, d_wtlh);
    cudaGetSymbolAddress((void**)&wtll, d_wtll);
    cudaGetSymbolAddress((void**)&s1,   d_s1);
    cudaGetSymbolAddress((void**)&r1,   d_r1);
    cudaGetSymbolAddress((void**)&c1,   d_c1);
    cudaGetSymbolAddress((void**)&s2,   d_s2);
    cudaGetSymbolAddress((void**)&r2,   d_r2);
    cudaGetSymbolAddress((void**)&c2,   d_c2);

    cudaFuncSetAttribute(k_mmaS, cudaFuncAttributeMaxDynamicSharedMemorySize, SM_TOTAL);
    cudaFuncSetAttribute(k_mmaD, cudaFuncAttributeMaxDynamicSharedMemorySize, SM_TOTAL);
    cudaFuncSetAttribute(k_value, cudaFuncAttributeMaxDynamicSharedMemorySize, VAL_SMEM);

    // ---- weight conversion + counter zero + embed (one launch) ----
    k_wt_all<<<(ALL_TOTAL + 255) / 256, 256>>>(w1, w2, w3, wl, nodes, embed);

    // ---- degree / CSR precompute (layer-invariant, parallel scan) ----
    k_histB<<<(EE + EEG + 255) / 256, 256>>>(snd, rcv, gsnd, grcv);
    k_scanA<<<512, 256>>>();
    k_scanM<<<2, 256>>>();
    k_scanC<<<512, 256>>>();
    k_scatB<<<(EE + EEG + 255) / 256, 256>>>(snd, rcv, gsnd, grcv);

    // ---- 7 GNN layers ----
    for (int i = 0; i < 7; i++) {
        k_aggB<<<2 * NN * 32 / 256, 256>>>();
        k_mmaD<<<1024, 256, SM_TOTAL>>>(
            mHi, mLo, wt1h + (size_t)i * 16384, wt1l + (size_t)i * 16384,
            b1 + i * 128, c1, r1, mHi, mLo,
            gHi, gLo, wt2h + (size_t)i * 16384, wt2l + (size_t)i * 16384,
            b2 + i * 128, c2, r2, gHi, gLo);
        int last = (i == 6);
        k_mmaS<<<512, 256, SM_TOTAL>>>(mHi, mLo, gHi, gLo,
                                       wt3h + (size_t)i * 32768, wt3l + (size_t)i * 32768,
                                       256, b3 + i * 128, nullptr, nullptr, 1,
                                       last ? h : nullptr, h16,
                                       last ? mHi : nullptr, last ? mLo : nullptr);
    }

    // ---- policy head: lg = h @ w_logit + b_logit (fp32 out) ----
    k_mmaS<<<512, 256, SM_TOTAL>>>(mHi, mLo, nullptr, nullptr, wtlh, wtll,
                                   128, bl, nullptr, nullptr, 0,
                                   lg, nullptr, nullptr, nullptr);
    k_edge_logits<<<(EE * 32) / 256, 256>>>(lg, snd, rcv, out);

    // ---- value head (fused) ----
    k_value<<<32, 256, VAL_SMEM>>>(h, ew, eb, wo, bo, out);
}

// round 17
// speedup vs baseline: 1.2892x; 1.0010x over previous
#include <cuda_runtime.h>
#include <cuda_bf16.h>
#include <cuda_fp16.h>
#include <math.h>
#include <stdint.h>

#define NN   65536
#define BB   1024
#define EE   2097152
#define EEG  524288
#define DIM  128
#define NSM  148

// ======================= portable PTX helpers ================================
__device__ __forceinline__ uint32_t smem_to_u32(const void* p) {
    uint32_t a;
    asm("{ .reg .u64 t; cvta.to.shared.u64 t, %1; cvt.u32.u64 %0, t; }" : "=r"(a) : "l"(p));
    return a;
}

__device__ __forceinline__ void ldsm4(uint32_t* r, uint32_t addr) {
    asm volatile("ldmatrix.sync.aligned.m8n8.x4.shared.b16 {%0,%1,%2,%3}, [%4];"
                 : "=r"(r[0]), "=r"(r[1]), "=r"(r[2]), "=r"(r[3]) : "r"(addr));
}

__device__ __forceinline__ void mma16816(float* c, const uint32_t* a, const uint32_t* b) {
    asm volatile("mma.sync.aligned.m16n8k16.row.col.f32.bf16.bf16.f32 "
                 "{%0,%1,%2,%3}, {%4,%5,%6,%7}, {%8,%9}, {%0,%1,%2,%3};"
                 : "+f"(c[0]), "+f"(c[1]), "+f"(c[2]), "+f"(c[3])
                 : "r"(a[0]), "r"(a[1]), "r"(a[2]), "r"(a[3]), "r"(b[0]), "r"(b[1]));
}

__device__ __forceinline__ void cp_async16(uint32_t dst, const void* src) {
    asm volatile("cp.async.cg.shared.global [%0], [%1], 16;" :: "r"(dst), "l"(src) : "memory");
}

// ======================= static scratch ======================================
__device__ float  d_h  [(size_t)NN * DIM];   // node features fp32 (last layer; value head — REQUIRED fp32, see R16)
__device__ __half d_h16[(size_t)NN * DIM];   // node features fp16 (aggregation gather source)
__device__ float  d_lg [(size_t)NN * DIM];   // logit-head features (fp32 — REQUIRED, see R10)

__device__ __nv_bfloat16 d_mHi[(size_t)NN * DIM], d_mLo[(size_t)NN * DIM];
__device__ __nv_bfloat16 d_gHi[(size_t)NN * DIM], d_gLo[(size_t)NN * DIM];

// converted transposed weights (bf16 hi/lo), layout [n][K]
__device__ __nv_bfloat16 d_wt1h[7*128*128], d_wt1l[7*128*128];
__device__ __nv_bfloat16 d_wt2h[7*128*128], d_wt2l[7*128*128];
__device__ __nv_bfloat16 d_wt3h[7*128*256], d_wt3l[7*128*256];
__device__ __nv_bfloat16 d_wtlh[128*128],   d_wtll[128*128];

__device__ int d_csrM[EE];
__device__ int d_csrG[EEG];
__device__ int d_offM[NN + 1];
__device__ int d_offG[NN + 1];
__device__ int d_curM[NN];
__device__ int d_curG[NN];
__device__ int d_cntOutM[NN], d_cntInM[NN], d_cntOutG[NN], d_cntInG[NN];
__device__ float d_s1[NN], d_r1[NN], d_c1[NN];
__device__ float d_s2[NN], d_r2[NN], d_c2[NN];
__device__ int d_psum[512];
__device__ int d_pbase[512];

// ======== weight convert + counter zero + embed->fp16 (one launch) ==========
#define WT_S1 (7*16384)
#define WT_S3 (7*32768)
#define WT_TOTAL (2*WT_S1 + WT_S3 + 16384)
#define ALL_TOTAL (WT_TOTAL + NN*16)
__global__ void k_wt_all(const float* __restrict__ w1, const float* __restrict__ w2,
                         const float* __restrict__ w3, const float* __restrict__ wl,
                         const int* __restrict__ nodes, const float* __restrict__ embed) {
    int id = blockIdx.x * blockDim.x + threadIdx.x;
    if (id < NN) { d_cntOutM[id] = 0; d_cntInM[id] = 0; d_cntOutG[id] = 0; d_cntInG[id] = 0; }
    float v;
    __nv_bfloat16 *hi, *lo;
    int oidx;
    if (id < WT_S1) {
        int layer = id >> 14, w = id & 16383;
        int n = w >> 7, k = w & 127;
        v = w1[(size_t)(layer << 14) + k * 128 + n];
        hi = d_wt1h; lo = d_wt1l; oidx = (layer << 14) + n * 128 + k;
    } else if (id < 2 * WT_S1) {
        int id2 = id - WT_S1;
        int layer = id2 >> 14, w = id2 & 16383;
        int n = w >> 7, k = w & 127;
        v = w2[(size_t)(layer << 14) + k * 128 + n];
        hi = d_wt2h; lo = d_wt2l; oidx = (layer << 14) + n * 128 + k;
    } else if (id < 2 * WT_S1 + WT_S3) {
        int id3 = id - 2 * WT_S1;
        int layer = id3 >> 15, w = id3 & 32767;
        int n = w >> 8, k = w & 255;
        v = w3[(size_t)(layer << 15) + k * 128 + n];
        hi = d_wt3h; lo = d_wt3l; oidx = (layer << 15) + n * 256 + k;
    } else if (id < WT_TOTAL) {
        int id4 = id - (2 * WT_S1 + WT_S3);
        int n = id4 >> 7, k = id4 & 127;
        v = wl[k * 128 + n];
        hi = d_wtlh; lo = d_wtll; oidx = n * 128 + k;
    } else if (id < ALL_TOTAL) {
        int e = id - WT_TOTAL;
        int node = e >> 4, seg = e & 15;
        const float* er = embed + (size_t)nodes[node] * 128 + seg * 8;
        __half hh[8];
#pragma unroll
        for (int j = 0; j < 8; j++) hh[j] = __float2half_rn(er[j]);
        *(uint4*)&d_h16[(size_t)node * 128 + seg * 8] = *(uint4*)hh;
        return;
    } else return;
    __nv_bfloat16 h = __float2bfloat16(v);
    hi[oidx] = h;
    lo[oidx] = __float2bfloat16(v - __bfloat162float(h));
}

// ======================= precompute ==========================================
__global__ void k_histB(const int* __restrict__ snd, const int* __restrict__ rcv,
                        const int* __restrict__ gsnd, const int* __restrict__ grcv) {
    int e = blockIdx.x * blockDim.x + threadIdx.x;
    if (e < EE) {
        atomicAdd(&d_cntOutM[snd[e]], 1); atomicAdd(&d_cntInM[rcv[e]], 1);
    } else if (e < EE + EEG) {
        int g = e - EE;
        atomicAdd(&d_cntOutG[gsnd[g]], 1); atomicAdd(&d_cntInG[grcv[g]], 1);
    }
}

__global__ void k_scanA() {
    int set = blockIdx.x >> 8;
    int t = threadIdx.x;
    int i = (blockIdx.x & 255) * 256 + t;
    const int* cnt  = set ? d_cntInG  : d_cntInM;
    const int* cntO = set ? d_cntOutG : d_cntOutM;
    float* sA = set ? d_s2 : d_s1;
    float* cA = set ? d_c2 : d_c1;
    float* rA = set ? d_r2 : d_r1;
    int cv = cnt[i];
    float sv = rsqrtf((float)(cntO[i] + 1));
    sA[i] = sv;
    cA[i] = sv;
    rA[i] = rsqrtf((float)(cv + 1));
    __shared__ int red[256];
    red[t] = cv;
    __syncthreads();
    for (int d = 128; d > 0; d >>= 1) {
        if (t < d) red[t] += red[t + d];
        __syncthreads();
    }
    if (t == 0) d_psum[blockIdx.x] = red[0];
}

__global__ void k_scanM() {
    int set = blockIdx.x;
    int t = threadIdx.x;
    __shared__ int ps[256];
    int v = d_psum[set * 256 + t];
    ps[t] = v;
    __syncthreads();
    for (int d = 1; d < 256; d <<= 1) {
        int x = 0;
        if (t >= d) x = ps[t - d];
        __syncthreads();
        ps[t] += x;
        __syncthreads();
    }
    d_pbase[set * 256 + t] = ps[t] - v;
    if (t == 255) {
        int* off = set ? d_offG : d_offM;
        off[NN] = ps[255];
    }
}

__global__ void k_scanC() {
    int set = blockIdx.x >> 8;
    int b = blockIdx.x & 255;
    int t = threadIdx.x;
    int i = b * 256 + t;
    const int* cnt = set ? d_cntInG : d_cntInM;
    int* off = set ? d_offG : d_offM;
    int* cur = set ? d_curG : d_curM;
    __shared__ int ps[256];
    int v = cnt[i];
    ps[t] = v;
    __syncthreads();
    for (int d = 1; d < 256; d <<= 1) {
        int x = 0;
        if (t >= d) x = ps[t - d];
        __syncthreads();
        ps[t] += x;
        __syncthreads();
    }
    int excl = ps[t] - v + d_pbase[set * 256 + b];
    off[i] = excl;
    cur[i] = excl;
}

__global__ void k_scatB(const int* __restrict__ snd, const int* __restrict__ rcv,
                        const int* __restrict__ gsnd, const int* __restrict__ grcv) {
    int e = blockIdx.x * blockDim.x + threadIdx.x;
    if (e < EE) {
        int s = snd[e], r = rcv[e];
        int p = atomicAdd(&d_curM[r], 1);
        d_csrM[p] = s;
        atomicAdd(&d_c1[r], d_s1[s]);
    } else if (e < EE + EEG) {
        int g = e - EE;
        int s = gsnd[g], r = grcv[g];
        int p = atomicAdd(&d_curG[r], 1);
        d_csrG[p] = s;
        atomicAdd(&d_c2[r], d_s2[s]);
    }
}

// ======================= pull aggregation (fp16 gather, unroll-8) ============
__device__ __forceinline__ void fma_h16(float4& acc, uint2 v, float c) {
    float2 a = __half22float2(*(__half2*)&v.x);
    float2 b = __half22float2(*(__half2*)&v.y);
    acc.x = fmaf(a.x, c, acc.x);
    acc.y = fmaf(a.y, c, acc.y);
    acc.z = fmaf(b.x, c, acc.z);
    acc.w = fmaf(b.y, c, acc.w);
}

__global__ void k_aggB() {
    int gw   = (blockIdx.x * blockDim.x + threadIdx.x) >> 5;  // 0 .. 2*NN-1
    int lane = threadIdx.x & 31;
    int isG  = gw >= NN;
    int node = gw - (isG ? NN : 0);
    if (gw >= 2 * NN) return;
    const int* off = isG ? d_offG : d_offM;
    const int* csr = isG ? d_csrG : d_csrM;
    const float* sn = isG ? d_s2 : d_s1;
    __nv_bfloat16* oHi = isG ? d_gHi : d_mHi;
    __nv_bfloat16* oLo = isG ? d_gLo : d_mLo;
    const __half* h16 = d_h16;

    float s0 = sn[node];
    float4 acc = {0.f, 0.f, 0.f, 0.f};
    uint2 sv = *(const uint2*)(h16 + (size_t)node * 128 + lane * 4);
    fma_h16(acc, sv, s0);
    int e  = off[node];
    int e1 = off[node + 1];
    for (; e + 8 <= e1; e += 8) {
        int ix[8];
        float cs[8];
#pragma unroll
        for (int j = 0; j < 8; j++) ix[j] = csr[e + j];
#pragma unroll
        for (int j = 0; j < 8; j++) cs[j] = sn[ix[j]];
        uint2 vv[8];
#pragma unroll
        for (int j = 0; j < 8; j++)
            vv[j] = *(const uint2*)(h16 + (size_t)ix[j] * 128 + lane * 4);
#pragma unroll
        for (int j = 0; j < 8; j++) fma_h16(acc, vv[j], cs[j]);
    }
    for (; e + 4 <= e1; e += 4) {
        int i0 = csr[e], i1 = csr[e + 1], i2 = csr[e + 2], i3 = csr[e + 3];
        float c0 = sn[i0], c1 = sn[i1], c2 = sn[i2], c3 = sn[i3];
        uint2 v0 = *(const uint2*)(h16 + (size_t)i0 * 128 + lane * 4);
        uint2 v1 = *(const uint2*)(h16 + (size_t)i1 * 128 + lane * 4);
        uint2 v2 = *(const uint2*)(h16 + (size_t)i2 * 128 + lane * 4);
        uint2 v3 = *(const uint2*)(h16 + (size_t)i3 * 128 + lane * 4);
        fma_h16(acc, v0, c0);
        fma_h16(acc, v1, c1);
        fma_h16(acc, v2, c2);
        fma_h16(acc, v3, c3);
    }
    for (; e < e1; e++) {
        int s = csr[e];
        uint2 v = *(const uint2*)(h16 + (size_t)s * 128 + lane * 4);
        fma_h16(acc, v, sn[s]);
    }
    __nv_bfloat16 hv[4], lv[4];
    float av[4] = {acc.x, acc.y, acc.z, acc.w};
#pragma unroll
    for (int j = 0; j < 4; j++) {
        hv[j] = __float2bfloat16(av[j]);
        lv[j] = __float2bfloat16(av[j] - __bfloat162float(hv[j]));
    }
    size_t p = (size_t)node * 128 + lane * 4;
    *(uint2*)&oHi[p] = *(uint2*)hv;
    *(uint2*)&oLo[p] = *(uint2*)lv;
}

// ======================= persistent HMMA GEMM ================================
// Grid of NSM blocks; tiles grid-strided; cp.async pipeline flows across tiles.
#define SLICE_BYTES 65536
#define SM_TOTAL    131072

struct Seg {
    const __nv_bfloat16 *aHi, *aLo, *gHi, *gLo, *wtHi, *wtLo;
    const float *bias, *crow, *rrow;
    float* outF;
    __half* outH16;
    __nv_bfloat16 *outHi, *outLo;
    int K, relu, ntiles;
};

__device__ __forceinline__ void stage_for(const Seg& s1, const Seg& s2,
                                          int tile, int slice, uint32_t sbuf, int tid) {
    bool one = tile < s1.ntiles;
    const Seg& sg = one ? s1 : s2;
    int rowBase = (one ? tile : tile - s1.ntiles) * 128;
    int c = slice >> 1, ks = slice & 1;
    const __nv_bfloat16* Ah = c ? sg.gHi : sg.aHi;
    const __nv_bfloat16* Al = c ? sg.gLo : sg.aLo;
    int K = sg.K;
#pragma unroll
    for (int j = 0; j < 16; j++) {
        int tile4 = j >> 2;
        int cidx = tid + (j & 3) * 256;
        int r = cidx >> 3, ch = cidx & 7;
        uint32_t dst = sbuf + tile4 * 16384 + (uint32_t)r * 128 +
                       (uint32_t)((ch * 16) ^ ((r & 7) << 4));
        const __nv_bfloat16* src;
        if (tile4 == 0)      src = Ah      + (size_t)(rowBase + r) * 128 + ks * 64 + ch * 8;
        else if (tile4 == 1) src = Al      + (size_t)(rowBase + r) * 128 + ks * 64 + ch * 8;
        else if (tile4 == 2) src = sg.wtHi + (size_t)r * K + c * 128 + ks * 64 + ch * 8;
        else                 src = sg.wtLo + (size_t)r * K + c * 128 + ks * 64 + ch * 8;
        cp_async16(dst, src);
    }
    asm volatile("cp.async.commit_group;" ::: "memory");
}

__device__ __forceinline__ void mma_compute_slice(
    uint32_t base, int ra_base, uint32_t kxA, uint32_t xorA,
    int rb_base, uint32_t kxB, uint32_t xorB, float acc[16][4]) {
#pragma unroll
    for (int ka = 0; ka < 4; ka++) {
        uint32_t fAh[2][4], fAl[2][4];
#pragma unroll
        for (int ma = 0; ma < 2; ma++) {
            uint32_t off = (uint32_t)(ra_base + ma * 16) * 128 +
                           (((uint32_t)(ka * 32) + kxA) ^ xorA);
            ldsm4(fAh[ma], base + off);
            ldsm4(fAl[ma], base + 16384 + off);
        }
#pragma unroll
        for (int nb = 0; nb < 4; nb++) {
            uint32_t off = (uint32_t)(rb_base + nb * 16) * 128 +
                           (((uint32_t)(ka * 32) + kxB) ^ xorB);
            uint32_t wh[4], wl[4];
            ldsm4(wh, base + 32768 + off);
            ldsm4(wl, base + 49152 + off);
#pragma unroll
            for (int ma = 0; ma < 2; ma++) {
                float* a0 = acc[ma * 8 + nb * 2];
                float* a1 = acc[ma * 8 + nb * 2 + 1];
                mma16816(a0, fAh[ma], wh);
                mma16816(a1, fAh[ma], wh + 2);
                mma16816(a0, fAl[ma], wh);
                mma16816(a1, fAl[ma], wh + 2);
                mma16816(a0, fAh[ma], wl);
                mma16816(a1, fAh[ma], wl + 2);
            }
        }
    }
}

__device__ __forceinline__ void epilogue_for(const Seg& sg, int lt, float acc[16][4],
                                             int m0, int n0, int l) {
    int gid = l >> 2, tig = l & 3;
    int rowBase = lt * 128;
#pragma unroll
    for (int ma = 0; ma < 2; ma++) {
        int r0 = rowBase + m0 + ma * 16 + gid;
        int r1 = r0 + 8;
        float cm0 = sg.crow ? sg.crow[r0] : 1.f, rm0 = sg.rrow ? sg.rrow[r0] : 1.f;
        float cm1 = sg.crow ? sg.crow[r1] : 1.f, rm1 = sg.rrow ? sg.rrow[r1] : 1.f;
#pragma unroll
        for (int na = 0; na < 8; na++) {
            int col = n0 + na * 8 + tig * 2;
            float b0 = sg.bias[col], b1 = sg.bias[col + 1];
            float* ac = acc[ma * 8 + na];
            float o00 = (ac[0] + b0 * cm0) * rm0;
            float o01 = (ac[1] + b1 * cm0) * rm0;
            float o10 = (ac[2] + b0 * cm1) * rm1;
            float o11 = (ac[3] + b1 * cm1) * rm1;
            if (sg.relu) {
                o00 = fmaxf(o00, 0.f); o01 = fmaxf(o01, 0.f);
                o10 = fmaxf(o10, 0.f); o11 = fmaxf(o11, 0.f);
            }
            if (sg.outH16) {
                __half2 q0 = __floats2half2_rn(o00, o01);
                __half2 q1 = __floats2half2_rn(o10, o11);
                *(__half2*)&sg.outH16[(size_t)r0 * 128 + col] = q0;
                *(__half2*)&sg.outH16[(size_t)r1 * 128 + col] = q1;
            }
            if (sg.outF) {
                *(float2*)&sg.outF[(size_t)r0 * 128 + col] = make_float2(o00, o01);
                *(float2*)&sg.outF[(size_t)r1 * 128 + col] = make_float2(o10, o11);
            }
            if (sg.outHi) {
                __nv_bfloat16 h00 = __float2bfloat16(o00), h01 = __float2bfloat16(o01);
                __nv_bfloat16 h10 = __float2bfloat16(o10), h11 = __float2bfloat16(o11);
                __nv_bfloat162 hp0; hp0.x = h00; hp0.y = h01;
                __nv_bfloat162 hp1; hp1.x = h10; hp1.y = h11;
                __nv_bfloat162 lp0;
                lp0.x = __float2bfloat16(o00 - __bfloat162float(h00));
                lp0.y = __float2bfloat16(o01 - __bfloat162float(h01));
                __nv_bfloat162 lp1;
                lp1.x = __float2bfloat16(o10 - __bfloat162float(h10));
                lp1.y = __float2bfloat16(o11 - __bfloat162float(h11));
                *(__nv_bfloat162*)&sg.outHi[(size_t)r0 * 128 + col] = hp0;
                *(__nv_bfloat162*)&sg.outHi[(size_t)r1 * 128 + col] = hp1;
                *(__nv_bfloat162*)&sg.outLo[(size_t)r0 * 128 + col] = lp0;
                *(__nv_bfloat162*)&sg.outLo[(size_t)r1 * 128 + col] = lp1;
            }
        }
    }
}

__global__ void __launch_bounds__(256)
k_mmaP(Seg s1, Seg s2) {
    extern __shared__ __align__(16) char smem[];
    uint32_t sb = smem_to_u32(smem);
    int ntiles = s1.ntiles + s2.ntiles;
    int tid = threadIdx.x;
    int wid = tid >> 5;
    int l   = tid & 31;
    int m0 = (wid >> 1) * 32;
    int n0 = (wid & 1) * 64;
    int ra_base = m0 + (l & 7) + ((l >> 3) & 1) * 8;
    uint32_t kxA = ((l >> 4) & 1) * 16;
    uint32_t xorA = (uint32_t)((ra_base & 7) << 4);
    int rb_base = n0 + (l & 7) + ((l >> 4) & 1) * 8;
    uint32_t kxB = ((l >> 3) & 1) * 16;
    uint32_t xorB = (uint32_t)((rb_base & 7) << 4);

    int t = blockIdx.x;
    if (t >= ntiles) return;
    stage_for(s1, s2, t, 0, sb, tid);
    int buf = 0;
    for (; t < ntiles; t += gridDim.x) {
        bool one = t < s1.ntiles;
        int K = one ? s1.K : s2.K;
        int nsl = K >> 6;
        float acc[16][4];
#pragma unroll
        for (int i = 0; i < 16; i++)
#pragma unroll
            for (int j = 0; j < 4; j++) acc[i][j] = 0.f;

        for (int s = 0; s < nsl; s++) {
            int nt = (s + 1 < nsl) ? t : t + (int)gridDim.x;
            int ns = (s + 1 < nsl) ? s + 1 : 0;
            if (nt < ntiles) {
                stage_for(s1, s2, nt, ns, sb + (buf ^ 1) * SLICE_BYTES, tid);
                asm volatile("cp.async.wait_group 1;" ::: "memory");
            } else {
                asm volatile("cp.async.wait_group 0;" ::: "memory");
            }
            __syncthreads();
            mma_compute_slice(sb + buf * SLICE_BYTES,
                              ra_base, kxA, xorA, rb_base, kxB, xorB, acc);
            __syncthreads();
            buf ^= 1;
        }
        // epilogue overlaps with the already-issued staging of the next tile
        epilogue_for(one ? s1 : s2, one ? t : t - s1.ntiles, acc, m0, n0, l);
    }
}

// ======================= edge logits (fp32 lg — required) ====================
__global__ void k_edge_logits(const float* __restrict__ lg, const int* __restrict__ snd,
                              const int* __restrict__ rcv, float* __restrict__ out) {
    int gw   = (blockIdx.x * blockDim.x + threadIdx.x) >> 5;
    int lane = threadIdx.x & 31;
    if (gw >= EE) return;
    const float4* l4 = (const float4*)lg;
    int s = snd[gw], r = rcv[gw];
    float4 a = l4[(size_t)s * 32 + lane];
    float4 b = l4[(size_t)r * 32 + lane];
    float p = a.x * b.x + a.y * b.y + a.z * b.z + a.w * b.w;
#pragma unroll
    for (int o = 16; o > 0; o >>= 1) p += __shfl_down_sync(0xffffffffu, p, o);
    if (lane == 0) out[gw] = p;
}

// ======================= fused value head (fp32 h — required) ================
#define VAL_SMEM (128*128*4 + 2*32*128*4)   // W (64KB) + v ping-pong (32KB)

__global__ void __launch_bounds__(256)
k_value(const float* __restrict__ h, const float* __restrict__ ew,
        const float* __restrict__ eb, const float* __restrict__ wo,
        const float* __restrict__ bo, float* __restrict__ out) {
    extern __shared__ __align__(16) float vsm[];
    float* Ws  = vsm;
    float* vb0 = vsm + 16384;
    float* vb1 = vb0 + 4096;
    int tid = threadIdx.x;
    int g0 = blockIdx.x * 32;

    for (int idx = tid; idx < 32 * 128; idx += 256) {
        int g = idx >> 7, col = idx & 127;
        const float* hp = h + ((size_t)(g0 + g) * 64 + 1) * 128 + col;
        float acc = 0.f;
        for (int j = 0; j < 63; j++) acc += hp[j * 128];
        vb0[idx] = acc * (1.f / 63.f);
    }

    float* cur = vb0;
    float* nxt = vb1;
    for (int layer = 0; layer < 5; layer++) {
        __syncthreads();
        for (int idx = tid; idx < 128 * 32; idx += 256)
            ((float4*)Ws)[idx] = ((const float4*)(ew + (size_t)layer * 16384))[idx];
        __syncthreads();
        for (int idx = tid; idx < 32 * 32; idx += 256) {
            int g = idx >> 5, cg = (idx & 31) * 4;
            const float* vr = &cur[g * 128];
            float4 acc = *(const float4*)&eb[layer * 128 + cg];
            for (int k = 0; k < 128; k++) {
                float av = vr[k];
                float4 w = *(const float4*)&Ws[k * 128 + cg];
                acc.x = fmaf(av, w.x, acc.x);
                acc.y = fmaf(av, w.y, acc.y);
                acc.z = fmaf(av, w.z, acc.z);
                acc.w = fmaf(av, w.w, acc.w);
            }
            acc.x = fmaxf(acc.x, 0.f); acc.y = fmaxf(acc.y, 0.f);
            acc.z = fmaxf(acc.z, 0.f); acc.w = fmaxf(acc.w, 0.f);
            *(float4*)&nxt[g * 128 + cg] = acc;
        }
        float* t = cur; cur = nxt; nxt = t;
    }
    __syncthreads();

    int w = tid >> 5, l = tid & 31;
    for (int sub = 0; sub < 4; sub++) {
        int g = w * 4 + sub;
        const float* vr = &cur[g * 128];
        float p = vr[l] * wo[l] + vr[l + 32] * wo[l + 32] +
                  vr[l + 64] * wo[l + 64] + vr[l + 96] * wo[l + 96];
#pragma unroll
        for (int o = 16; o > 0; o >>= 1) p += __shfl_down_sync(0xffffffffu, p, o);
        if (l == 0) out[EE + g0 + g] = tanhf(p + bo[0]);
    }
}

// ======================= host launcher =======================================
extern "C" void kernel_launch(void* const* d_in, const int* in_sizes, int n_in,
                              void* d_out, int out_size) {
    const int*   nodes = (const int*)d_in[0];
    const int*   snd   = (const int*)d_in[1];
    const int*   rcv   = (const int*)d_in[2];
    const int*   gsnd  = (const int*)d_in[3];
    const int*   grcv  = (const int*)d_in[4];
    const float* embed = (const float*)d_in[6];
    const float* w1    = (const float*)d_in[7];
    const float* b1    = (const float*)d_in[8];
    const float* w2    = (const float*)d_in[9];
    const float* b2    = (const float*)d_in[10];
    const float* w3    = (const float*)d_in[11];
    const float* b3    = (const float*)d_in[12];
    const float* wl    = (const float*)d_in[13];
    const float* bl    = (const float*)d_in[14];
    const float* ew    = (const float*)d_in[15];
    const float* eb    = (const float*)d_in[16];
    const float* wo    = (const float*)d_in[17];
    const float* bo    = (const float*)d_in[18];
    float* out = (float*)d_out;

    float *h, *lg, *s1, *r1, *c1, *s2, *r2, *c2;
    __half* h16;
    __nv_bfloat16 *mHi, *mLo, *gHi, *gLo;
    __nv_bfloat16 *wt1h, *wt1l, *wt2h, *wt2l, *wt3h, *wt3l, *wtlh, *wtll;
    cudaGetSymbolAddress((void**)&h,    d_h);
    cudaGetSymbolAddress((void**)&h16,  d_h16);
    cudaGetSymbolAddress((void**)&lg,   d_lg);
    cudaGetSymbolAddress((void**)&mHi,  d_mHi);
    cudaGetSymbolAddress((void**)&mLo,  d_mLo);
    cudaGetSymbolAddress((void**)&gHi,  d_gHi);
    cudaGetSymbolAddress((void**)&gLo,  d_gLo);
    cudaGetSymbolAddress((void**)&wt1h, d_wt1h);
    cudaGetSymbolAddress((void**)&wt1l, d_wt1l);
    cudaGetSymbolAddress((void**)&wt2h, d_wt2h);
    cudaGetSymbolAddress((void**)&wt2l, d_wt2l);
    cudaGetSymbolAddress((void**)&wt3h, d_wt3h);
    cudaGetSymbolAddress((void**)&wt3l, d_wt3l);
    cudaGetSymbolAddress((void**)&wtlh, d_wtlh);
    cudaGetSymbolAddress((void**)&wtll, d_wtll);
    cudaGetSymbolAddress((void**)&s1,   d_s1);
    cudaGetSymbolAddress((void**)&r1,   d_r1);
    cudaGetSymbolAddress((void**)&c1,   d_c1);
    cudaGetSymbolAddress((void**)&s2,   d_s2);
    cudaGetSymbolAddress((void**)&r2,   d_r2);
    cudaGetSymbolAddress((void**)&c2,   d_c2);

    cudaFuncSetAttribute(k_mmaP, cudaFuncAttributeMaxDynamicSharedMemorySize, SM_TOTAL);
    cudaFuncSetAttribute(k_value, cudaFuncAttributeMaxDynamicSharedMemorySize, VAL_SMEM);

    Seg zero;
    zero.aHi = zero.aLo = zero.gHi = zero.gLo = zero.wtHi = zero.wtLo = nullptr;
    zero.bias = zero.crow = zero.rrow = nullptr;
    zero.outF = nullptr; zero.outH16 = nullptr;
    zero.outHi = zero.outLo = nullptr;
    zero.K = 128; zero.relu = 0; zero.ntiles = 0;

    // ---- weight conversion + counter zero + embed (one launch) ----
    k_wt_all<<<(ALL_TOTAL + 255) / 256, 256>>>(w1, w2, w3, wl, nodes, embed);

    // ---- degree / CSR precompute (layer-invariant, parallel scan) ----
    k_histB<<<(EE + EEG + 255) / 256, 256>>>(snd, rcv, gsnd, grcv);
    k_scanA<<<512, 256>>>();
    k_scanM<<<2, 256>>>();
    k_scanC<<<512, 256>>>();
    k_scatB<<<(EE + EEG + 255) / 256, 256>>>(snd, rcv, gsnd, grcv);

    // ---- 7 GNN layers ----
    for (int i = 0; i < 7; i++) {
        k_aggB<<<2 * NN * 32 / 256, 256>>>();

        Seg sA = zero;
        sA.aHi = mHi; sA.aLo = mLo;
        sA.wtHi = wt1h + (size_t)i * 16384; sA.wtLo = wt1l + (size_t)i * 16384;
        sA.bias = b1 + i * 128; sA.crow = c1; sA.rrow = r1;
        sA.outHi = mHi; sA.outLo = mLo;
        sA.K = 128; sA.relu = 0; sA.ntiles = 512;
        Seg sB = zero;
        sB.aHi = gHi; sB.aLo = gLo;
        sB.wtHi = wt2h + (size_t)i * 16384; sB.wtLo = wt2l + (size_t)i * 16384;
        sB.bias = b2 + i * 128; sB.crow = c2; sB.rrow = r2;
        sB.outHi = gHi; sB.outLo = gLo;
        sB.K = 128; sB.relu = 0; sB.ntiles = 512;
        k_mmaP<<<NSM, 256, SM_TOTAL>>>(sA, sB);

        int last = (i == 6);
        Seg sC = zero;
        sC.aHi = mHi; sC.aLo = mLo; sC.gHi = gHi; sC.gLo = gLo;
        sC.wtHi = wt3h + (size_t)i * 32768; sC.wtLo = wt3l + (size_t)i * 32768;
        sC.bias = b3 + i * 128;
        sC.outH16 = h16;
        sC.outF = last ? h : nullptr;                 // fp32 h for value head (R16)
        sC.outHi = last ? mHi : nullptr; sC.outLo = last ? mLo : nullptr;
        sC.K = 256; sC.relu = 1; sC.ntiles = 512;
        k_mmaP<<<NSM, 256, SM_TOTAL>>>(sC, zero);
    }

    // ---- policy head: lg = h @ w_logit + b_logit (fp32 out) ----
    Seg sL = zero;
    sL.aHi = mHi; sL.aLo = mLo;
    sL.wtHi = wtlh; sL.wtLo = wtll;
    sL.bias = bl;
    sL.outF = lg;
    sL.K = 128; sL.relu = 0; sL.ntiles = 512;
    k_mmaP<<<NSM, 256, SM_TOTAL>>>(sL, zero);
    k_edge_logits<<<(EE * 32) / 256, 256>>>(lg, snd, rcv, out);

    // ---- value head (fused, reads fp32 h) ----
    k_value<<<32, 256, VAL_SMEM>>>(h, ew, eb, wo, bo, out);
}